// round 5
// baseline (speedup 1.0000x reference)
#include <cuda_runtime.h>
#include <cstdint>

#define CB 2
#define CS 2048
#define CD 1024
#define CH 16
#define CHD 64
#define CBH (CB*CH)
#define CM (CB*CS)
#define OUT_ELEMS (CB*CS*CD)
#define ATTN_ELEMS ((size_t)CBH*CS*CS)
#define NKT (CS/128)   // 16 k-tiles per row

__device__ float g_q[CBH*CS*CHD];
__device__ float g_k[CBH*CS*CHD];
__device__ float g_v[CBH*CS*CHD];
__device__ float g_ctx[CBH*CS*CHD];
__device__ float g_attn_fb[(size_t)CBH*CS*CS];
__device__ float g_stat_max[(size_t)CBH*CS*NKT];
__device__ float g_stat_sum[(size_t)CBH*CS*NKT];
__device__ float g_row_m[CBH*CS];
__device__ float g_row_inv[CBH*CS];
__device__ int   g_mask_mode;

#define NEG_INF __int_as_float(0xff800000)

__global__ void detect_mask_kernel(const uint32_t* __restrict__ mask) {
    uint32_t w = mask[0];
    int mode = 0;
    if (w == 0x01010101u)      mode = 0;  // uint8 bool
    else if (w == 1u)          mode = 1;  // int32
    else if (w == 0x3F800000u) mode = 2;  // float32
    g_mask_mode = mode;
}

__device__ __forceinline__ uint32_t f2tf(float f) {
    uint32_t r;
    asm("cvt.rna.tf32.f32 %0, %1;" : "=r"(r) : "f"(f));
    return r;
}

__device__ __forceinline__ void mma8(float* c, const uint32_t* a, const uint32_t* b) {
    asm volatile(
        "mma.sync.aligned.m16n8k8.row.col.f32.tf32.tf32.f32 "
        "{%0,%1,%2,%3}, {%4,%5,%6,%7}, {%8,%9}, {%0,%1,%2,%3};"
        : "+f"(c[0]), "+f"(c[1]), "+f"(c[2]), "+f"(c[3])
        : "r"(a[0]), "r"(a[1]), "r"(a[2]), "r"(a[3]), "r"(b[0]), "r"(b[1]));
}

// ===========================================================================
// proj (unchanged from R4)
// ===========================================================================
__global__ void __launch_bounds__(256,2) proj_mma(
    const float* __restrict__ A, const float* __restrict__ W,
    const float* __restrict__ bias, float* __restrict__ dst)
{
    __shared__ uint32_t sA[2][16][132];
    __shared__ uint32_t sB[2][16][132];
    const int tid = threadIdx.x, warp = tid >> 5, lane = tid & 31;
    const int g = lane >> 2, tg = lane & 3;
    const int m0 = blockIdx.y * 128, n0 = blockIdx.x * 128;
    const int wm = (warp & 1) * 64, wn = (warp >> 1) * 32;

    const int ar_ = tid & 127, akst = tid >> 7;
    const float* Ap = A + (size_t)(m0 + ar_) * CD + akst * 8;
    const int bk_ = tid >> 4, bn_ = (tid & 15) * 8;
    const float* Bp = W + (size_t)bk_ * CD + n0 + bn_;

    float4 fa0, fa1, fb0, fb1;
    fa0 = *(const float4*)(Ap);  fa1 = *(const float4*)(Ap + 4);
    fb0 = *(const float4*)(Bp);  fb1 = *(const float4*)(Bp + 4);

    auto commit = [&](int buf) {
        const float* f0 = &fa0.x; const float* f1 = &fa1.x;
        #pragma unroll
        for (int j = 0; j < 4; ++j) {
            sA[buf][akst*8 + j][ar_]     = f2tf(f0[j]);
            sA[buf][akst*8 + 4 + j][ar_] = f2tf(f1[j]);
        }
        uint4 w0, w1;
        w0.x = f2tf(fb0.x); w0.y = f2tf(fb0.y); w0.z = f2tf(fb0.z); w0.w = f2tf(fb0.w);
        w1.x = f2tf(fb1.x); w1.y = f2tf(fb1.y); w1.z = f2tf(fb1.z); w1.w = f2tf(fb1.w);
        *(uint4*)&sB[buf][bk_][bn_]     = w0;
        *(uint4*)&sB[buf][bk_][bn_ + 4] = w1;
    };
    commit(0);
    __syncthreads();

    float acc[4][4][4] = {};
    int buf = 0;
    for (int c = 1; c <= 64; ++c) {
        float4 na0, na1, nb0, nb1;
        const bool more = c < 64;
        if (more) {
            int kc = c * 16;
            na0 = *(const float4*)(Ap + kc); na1 = *(const float4*)(Ap + kc + 4);
            nb0 = *(const float4*)(Bp + (size_t)kc * CD);
            nb1 = *(const float4*)(Bp + (size_t)kc * CD + 4);
        }
        #pragma unroll
        for (int ks = 0; ks < 2; ++ks) {
            uint32_t af[4][4], bf[4][2];
            #pragma unroll
            for (int i = 0; i < 4; ++i) {
                int m = wm + i*16 + g;
                af[i][0] = sA[buf][ks*8 + tg][m];
                af[i][1] = sA[buf][ks*8 + tg][m + 8];
                af[i][2] = sA[buf][ks*8 + tg + 4][m];
                af[i][3] = sA[buf][ks*8 + tg + 4][m + 8];
            }
            #pragma unroll
            for (int j = 0; j < 4; ++j) {
                int n = wn + j*8 + g;
                bf[j][0] = sB[buf][ks*8 + tg][n];
                bf[j][1] = sB[buf][ks*8 + tg + 4][n];
            }
            #pragma unroll
            for (int i = 0; i < 4; ++i)
                #pragma unroll
                for (int j = 0; j < 4; ++j)
                    mma8(acc[i][j], af[i], bf[j]);
        }
        if (more) {
            fa0 = na0; fa1 = na1; fb0 = nb0; fb1 = nb1;
            commit(buf ^ 1);
            __syncthreads();
            buf ^= 1;
        }
    }

    #pragma unroll
    for (int i = 0; i < 4; ++i) {
        int r0 = m0 + wm + i*16 + g;
        int r1 = r0 + 8;
        int b0i = r0 >> 11, s0 = r0 & (CS-1);
        int b1i = r1 >> 11, s1 = r1 & (CS-1);
        #pragma unroll
        for (int j = 0; j < 4; ++j) {
            int col = n0 + wn + j*8 + 2*tg;
            int h = col >> 6, hd = col & 63;
            float2 bb = *(const float2*)(bias + col);
            float2 o0 = { acc[i][j][0] + bb.x, acc[i][j][1] + bb.y };
            float2 o1 = { acc[i][j][2] + bb.x, acc[i][j][3] + bb.y };
            *(float2*)&dst[((size_t)(b0i*CH + h)*CS + s0)*CHD + hd] = o0;
            *(float2*)&dst[((size_t)(b1i*CH + h)*CS + s1)*CHD + hd] = o1;
        }
    }
}

// ===========================================================================
// qk: scores + per-(row, k-tile) softmax stats (max, sumexp).
// ===========================================================================
__global__ void __launch_bounds__(256,2) qk_mma(
    const void* __restrict__ maskp, float* __restrict__ scores)
{
    __shared__ uint32_t sA[2][16][132];
    __shared__ uint32_t sB[2][16][132];
    const int tid = threadIdx.x, warp = tid >> 5, lane = tid & 31;
    const int g = lane >> 2, tg = lane & 3;
    const int bh = blockIdx.z;
    const int q0 = blockIdx.y * 128, k0t = blockIdx.x * 128;
    const int wm = (warp & 1) * 64, wn = (warp >> 1) * 32;
    const float* Qb = g_q + (size_t)bh * CS * CHD;
    const float* Kb = g_k + (size_t)bh * CS * CHD;

    const int ar_ = tid & 127, akst = tid >> 7;
    const float* Ap = Qb + (size_t)(q0 + ar_) * CHD + akst * 8;
    const float* Bp = Kb + (size_t)(k0t + ar_) * CHD + akst * 8;

    float4 fa0, fa1, fb0, fb1;
    fa0 = *(const float4*)(Ap);  fa1 = *(const float4*)(Ap + 4);
    fb0 = *(const float4*)(Bp);  fb1 = *(const float4*)(Bp + 4);

    auto commit = [&](int buf) {
        const float* f0 = &fa0.x; const float* f1 = &fa1.x;
        const float* h0 = &fb0.x; const float* h1 = &fb1.x;
        #pragma unroll
        for (int j = 0; j < 4; ++j) {
            sA[buf][akst*8 + j][ar_]     = f2tf(f0[j]);
            sA[buf][akst*8 + 4 + j][ar_] = f2tf(f1[j]);
            sB[buf][akst*8 + j][ar_]     = f2tf(h0[j]);
            sB[buf][akst*8 + 4 + j][ar_] = f2tf(h1[j]);
        }
    };
    commit(0);
    __syncthreads();

    float acc[4][4][4] = {};
    int buf = 0;
    for (int c = 1; c <= 4; ++c) {
        float4 na0, na1, nb0, nb1;
        const bool more = c < 4;
        if (more) {
            int kc = c * 16;
            na0 = *(const float4*)(Ap + kc); na1 = *(const float4*)(Ap + kc + 4);
            nb0 = *(const float4*)(Bp + kc); nb1 = *(const float4*)(Bp + kc + 4);
        }
        #pragma unroll
        for (int ks = 0; ks < 2; ++ks) {
            uint32_t af[4][4], bf[4][2];
            #pragma unroll
            for (int i = 0; i < 4; ++i) {
                int m = wm + i*16 + g;
                af[i][0] = sA[buf][ks*8 + tg][m];
                af[i][1] = sA[buf][ks*8 + tg][m + 8];
                af[i][2] = sA[buf][ks*8 + tg + 4][m];
                af[i][3] = sA[buf][ks*8 + tg + 4][m + 8];
            }
            #pragma unroll
            for (int j = 0; j < 4; ++j) {
                int n = wn + j*8 + g;
                bf[j][0] = sB[buf][ks*8 + tg][n];
                bf[j][1] = sB[buf][ks*8 + tg + 4][n];
            }
            #pragma unroll
            for (int i = 0; i < 4; ++i)
                #pragma unroll
                for (int j = 0; j < 4; ++j)
                    mma8(acc[i][j], af[i], bf[j]);
        }
        if (more) {
            fa0 = na0; fa1 = na1; fb0 = nb0; fb1 = nb1;
            commit(buf ^ 1);
            __syncthreads();
            buf ^= 1;
        }
    }

    // --- epilogue: mask+scale into acc (in place), write raw scores ---
    const int mode = g_mask_mode;
    float* srow = scores + (size_t)bh * CS * CS;
    #pragma unroll
    for (int i = 0; i < 4; ++i) {
        int r0 = q0 + wm + i*16 + g;
        int r1 = r0 + 8;
        #pragma unroll
        for (int j = 0; j < 4; ++j) {
            int col = k0t + wn + j*8 + 2*tg;
            size_t off0 = (size_t)r0 * CS + col;
            size_t off1 = (size_t)r1 * CS + col;
            bool k00, k01, k10, k11;
            if (mode == 0) {
                uchar2 a = *(const uchar2*)((const unsigned char*)maskp + off0);
                uchar2 b = *(const uchar2*)((const unsigned char*)maskp + off1);
                k00 = a.x; k01 = a.y; k10 = b.x; k11 = b.y;
            } else if (mode == 1) {
                int2 a = *(const int2*)((const int*)maskp + off0);
                int2 b = *(const int2*)((const int*)maskp + off1);
                k00 = a.x; k01 = a.y; k10 = b.x; k11 = b.y;
            } else {
                float2 a = *(const float2*)((const float*)maskp + off0);
                float2 b = *(const float2*)((const float*)maskp + off1);
                k00 = a.x != 0.f; k01 = a.y != 0.f; k10 = b.x != 0.f; k11 = b.y != 0.f;
            }
            acc[i][j][0] = k00 ? acc[i][j][0]*0.125f : NEG_INF;
            acc[i][j][1] = k01 ? acc[i][j][1]*0.125f : NEG_INF;
            acc[i][j][2] = k10 ? acc[i][j][2]*0.125f : NEG_INF;
            acc[i][j][3] = k11 ? acc[i][j][3]*0.125f : NEG_INF;
            *(float2*)(srow + off0) = *(float2*)&acc[i][j][0];
            *(float2*)(srow + off1) = *(float2*)&acc[i][j][2];
        }
    }

    // --- tile softmax stats: per-row max and sumexp over these 128 cols ---
    float* sred = (float*)sA;          // [4][128]
    float* ssum = sred + 512;          // [4][128]
    const int wnIdx = warp >> 1;
    __syncthreads();                   // done with sA/sB as mma operands

    float rmax[4][2];
    #pragma unroll
    for (int i = 0; i < 4; ++i)
        #pragma unroll
        for (int h = 0; h < 2; ++h) {
            float m = NEG_INF;
            #pragma unroll
            for (int j = 0; j < 4; ++j) {
                m = fmaxf(m, acc[i][j][2*h]);
                m = fmaxf(m, acc[i][j][2*h+1]);
            }
            m = fmaxf(m, __shfl_xor_sync(0xffffffffu, m, 1));
            m = fmaxf(m, __shfl_xor_sync(0xffffffffu, m, 2));
            rmax[i][h] = m;
        }
    if (tg == 0) {
        #pragma unroll
        for (int i = 0; i < 4; ++i)
            #pragma unroll
            for (int h = 0; h < 2; ++h)
                sred[wnIdx*128 + wm + i*16 + h*8 + g] = rmax[i][h];
    }
    __syncthreads();
    #pragma unroll
    for (int i = 0; i < 4; ++i)
        #pragma unroll
        for (int h = 0; h < 2; ++h) {
            int rl = wm + i*16 + h*8 + g;
            float m = fmaxf(fmaxf(sred[rl], sred[128+rl]),
                            fmaxf(sred[256+rl], sred[384+rl]));
            rmax[i][h] = m;
        }
    float rsum[4][2];
    #pragma unroll
    for (int i = 0; i < 4; ++i)
        #pragma unroll
        for (int h = 0; h < 2; ++h) {
            float m = rmax[i][h];
            float s = 0.f;
            #pragma unroll
            for (int j = 0; j < 4; ++j) {
                float v0 = acc[i][j][2*h], v1 = acc[i][j][2*h+1];
                s += (v0 == NEG_INF) ? 0.f : __expf(v0 - m);
                s += (v1 == NEG_INF) ? 0.f : __expf(v1 - m);
            }
            s += __shfl_xor_sync(0xffffffffu, s, 1);
            s += __shfl_xor_sync(0xffffffffu, s, 2);
            rsum[i][h] = s;
        }
    if (tg == 0) {
        #pragma unroll
        for (int i = 0; i < 4; ++i)
            #pragma unroll
            for (int h = 0; h < 2; ++h)
                ssum[wnIdx*128 + wm + i*16 + h*8 + g] = rsum[i][h];
    }
    __syncthreads();
    if (wnIdx == 0 && tg == 0) {     // warps 0 (wm=0) and 1 (wm=64) cover all rows
        #pragma unroll
        for (int i = 0; i < 4; ++i)
            #pragma unroll
            for (int h = 0; h < 2; ++h) {
                int rl = wm + i*16 + h*8 + g;
                float s = ssum[rl] + ssum[128+rl] + ssum[256+rl] + ssum[384+rl];
                size_t sidx = ((size_t)bh*CS + q0 + rl)*NKT + blockIdx.x;
                g_stat_max[sidx] = rmax[i][h];
                g_stat_sum[sidx] = s;
            }
    }
}

// ===========================================================================
// stat_reduce: merge 16 tile stats per row -> row max M and 1/sum.
// ===========================================================================
__global__ void __launch_bounds__(256) stat_reduce()
{
    int idx = blockIdx.x * 256 + threadIdx.x;   // bh*CS + row
    const float* pm = g_stat_max + (size_t)idx * NKT;
    const float* ps = g_stat_sum + (size_t)idx * NKT;
    float M = NEG_INF;
    #pragma unroll
    for (int t = 0; t < NKT; ++t) M = fmaxf(M, pm[t]);
    float S = 0.f;
    #pragma unroll
    for (int t = 0; t < NKT; ++t) S += ps[t] * __expf(pm[t] - M);
    g_row_m[idx] = M;
    g_row_inv[idx] = 1.0f / S;
}

// ===========================================================================
// pv: reads raw scores, transforms to probs in-place (writes attn output),
// computes ctx = attn @ V. CTA 256x64.
// ===========================================================================
__global__ void __launch_bounds__(256,2) pv_mma(float* __restrict__ attn)
{
    __shared__ uint32_t sA[2][16][260];
    __shared__ uint32_t sB[2][16][68];
    const int tid = threadIdx.x, warp = tid >> 5, lane = tid & 31;
    const int g = lane >> 2, tg = lane & 3;
    const int bh = blockIdx.y, m0 = blockIdx.x * 256;
    const int wm = (warp & 3) * 64, wn = (warp >> 2) * 32;
    float* Ab = attn + (size_t)bh * CS * CS;
    const float* Vb = g_v + (size_t)bh * CS * CHD;

    const int r = m0 + tid;
    const float rm   = g_row_m[bh*CS + r];
    const float rinv = g_row_inv[bh*CS + r];
    float* Ap = Ab + (size_t)r * CS;
    const int bk_ = tid >> 4, bn_ = (tid & 15) * 4;
    const float* Bp = Vb + (size_t)bk_ * CHD + bn_;

    auto xf = [&](float4& v, float* dst) {
        v.x = __expf(v.x - rm) * rinv;
        v.y = __expf(v.y - rm) * rinv;
        v.z = __expf(v.z - rm) * rinv;
        v.w = __expf(v.w - rm) * rinv;
        *(float4*)dst = v;
    };

    float4 fa[4], fbv;
    #pragma unroll
    for (int q = 0; q < 4; ++q) {
        fa[q] = *(const float4*)(Ap + q*4);
        xf(fa[q], Ap + q*4);
    }
    fbv = *(const float4*)(Bp);

    auto commit = [&](int buf) {
        #pragma unroll
        for (int q = 0; q < 4; ++q) {
            const float* f = &fa[q].x;
            #pragma unroll
            for (int j = 0; j < 4; ++j)
                sA[buf][q*4 + j][tid] = f2tf(f[j]);
        }
        uint4 w;
        w.x = f2tf(fbv.x); w.y = f2tf(fbv.y); w.z = f2tf(fbv.z); w.w = f2tf(fbv.w);
        *(uint4*)&sB[buf][bk_][bn_] = w;
    };
    commit(0);
    __syncthreads();

    float acc[4][4][4] = {};
    int buf = 0;
    for (int c = 1; c <= 128; ++c) {
        float4 na[4], nb;
        const bool more = c < 128;
        if (more) {
            int kc = c * 16;
            #pragma unroll
            for (int q = 0; q < 4; ++q) {
                na[q] = *(const float4*)(Ap + kc + q*4);
                xf(na[q], Ap + kc + q*4);
            }
            nb = *(const float4*)(Bp + (size_t)kc * CHD);
        }
        #pragma unroll
        for (int ks = 0; ks < 2; ++ks) {
            uint32_t af[4][4], bf[4][2];
            #pragma unroll
            for (int i = 0; i < 4; ++i) {
                int m = wm + i*16 + g;
                af[i][0] = sA[buf][ks*8 + tg][m];
                af[i][1] = sA[buf][ks*8 + tg][m + 8];
                af[i][2] = sA[buf][ks*8 + tg + 4][m];
                af[i][3] = sA[buf][ks*8 + tg + 4][m + 8];
            }
            #pragma unroll
            for (int j = 0; j < 4; ++j) {
                int n = wn + j*8 + g;
                bf[j][0] = sB[buf][ks*8 + tg][n];
                bf[j][1] = sB[buf][ks*8 + tg + 4][n];
            }
            #pragma unroll
            for (int i = 0; i < 4; ++i)
                #pragma unroll
                for (int j = 0; j < 4; ++j)
                    mma8(acc[i][j], af[i], bf[j]);
        }
        if (more) {
            #pragma unroll
            for (int q = 0; q < 4; ++q) fa[q] = na[q];
            fbv = nb;
            commit(buf ^ 1);
            __syncthreads();
            buf ^= 1;
        }
    }

    float* ctxb = g_ctx + (size_t)bh * CS * CHD;
    #pragma unroll
    for (int i = 0; i < 4; ++i) {
        int r0 = m0 + wm + i*16 + g;
        int r1 = r0 + 8;
        #pragma unroll
        for (int j = 0; j < 4; ++j) {
            int col = wn + j*8 + 2*tg;
            float2 o0 = { acc[i][j][0], acc[i][j][1] };
            float2 o1 = { acc[i][j][2], acc[i][j][3] };
            *(float2*)&ctxb[(size_t)r0 * CHD + col] = o0;
            *(float2*)&ctxb[(size_t)r1 * CHD + col] = o1;
        }
    }
}

// ===========================================================================
// outproj (unchanged from R4)
// ===========================================================================
__global__ void __launch_bounds__(256,2) outproj_mma(
    const float* __restrict__ W, const float* __restrict__ bias, float* __restrict__ out)
{
    __shared__ uint32_t sA[2][16][132];
    __shared__ uint32_t sB[2][16][132];
    const int tid = threadIdx.x, warp = tid >> 5, lane = tid & 31;
    const int g = lane >> 2, tg = lane & 3;
    const int m0 = blockIdx.y * 128, n0 = blockIdx.x * 128;
    const int wm = (warp & 1) * 64, wn = (warp >> 1) * 32;

    const int ar_ = tid & 127, akst = tid >> 7;
    const int m = m0 + ar_;
    const int bidx = m >> 11, s = m & (CS-1);
    const float* ctxb = g_ctx + ((size_t)bidx*CH*CS + s) * CHD;
    const int bk_ = tid >> 4, bn_ = (tid & 15) * 8;
    const float* Bp = W + (size_t)bk_ * CD + n0 + bn_;

    auto fetchA = [&](int kc, float4& a0, float4& a1) {
        int kb = kc + akst * 8;
        const float* p = ctxb + (size_t)(kb >> 6) * CS * CHD + (kb & 63);
        a0 = *(const float4*)(p);
        a1 = *(const float4*)(p + 4);
    };

    float4 fa0, fa1, fb0, fb1;
    fetchA(0, fa0, fa1);
    fb0 = *(const float4*)(Bp); fb1 = *(const float4*)(Bp + 4);

    auto commit = [&](int buf) {
        const float* f0 = &fa0.x; const float* f1 = &fa1.x;
        #pragma unroll
        for (int j = 0; j < 4; ++j) {
            sA[buf][akst*8 + j][ar_]     = f2tf(f0[j]);
            sA[buf][akst*8 + 4 + j][ar_] = f2tf(f1[j]);
        }
        uint4 w0, w1;
        w0.x = f2tf(fb0.x); w0.y = f2tf(fb0.y); w0.z = f2tf(fb0.z); w0.w = f2tf(fb0.w);
        w1.x = f2tf(fb1.x); w1.y = f2tf(fb1.y); w1.z = f2tf(fb1.z); w1.w = f2tf(fb1.w);
        *(uint4*)&sB[buf][bk_][bn_]     = w0;
        *(uint4*)&sB[buf][bk_][bn_ + 4] = w1;
    };
    commit(0);
    __syncthreads();

    float acc[4][4][4] = {};
    int buf = 0;
    for (int c = 1; c <= 64; ++c) {
        float4 na0, na1, nb0, nb1;
        const bool more = c < 64;
        if (more) {
            int kc = c * 16;
            fetchA(kc, na0, na1);
            nb0 = *(const float4*)(Bp + (size_t)kc * CD);
            nb1 = *(const float4*)(Bp + (size_t)kc * CD + 4);
        }
        #pragma unroll
        for (int ks = 0; ks < 2; ++ks) {
            uint32_t af[4][4], bf[4][2];
            #pragma unroll
            for (int i = 0; i < 4; ++i) {
                int mm = wm + i*16 + g;
                af[i][0] = sA[buf][ks*8 + tg][mm];
                af[i][1] = sA[buf][ks*8 + tg][mm + 8];
                af[i][2] = sA[buf][ks*8 + tg + 4][mm];
                af[i][3] = sA[buf][ks*8 + tg + 4][mm + 8];
            }
            #pragma unroll
            for (int j = 0; j < 4; ++j) {
                int n = wn + j*8 + g;
                bf[j][0] = sB[buf][ks*8 + tg][n];
                bf[j][1] = sB[buf][ks*8 + tg + 4][n];
            }
            #pragma unroll
            for (int i = 0; i < 4; ++i)
                #pragma unroll
                for (int j = 0; j < 4; ++j)
                    mma8(acc[i][j], af[i], bf[j]);
        }
        if (more) {
            fa0 = na0; fa1 = na1; fb0 = nb0; fb1 = nb1;
            commit(buf ^ 1);
            __syncthreads();
            buf ^= 1;
        }
    }

    #pragma unroll
    for (int i = 0; i < 4; ++i) {
        int r0 = m0 + wm + i*16 + g;
        int r1 = r0 + 8;
        #pragma unroll
        for (int j = 0; j < 4; ++j) {
            int col = n0 + wn + j*8 + 2*tg;
            float2 bb = *(const float2*)(bias + col);
            float2 o0 = { acc[i][j][0] + bb.x, acc[i][j][1] + bb.y };
            float2 o1 = { acc[i][j][2] + bb.x, acc[i][j][3] + bb.y };
            *(float2*)&out[(size_t)r0 * CD + col] = o0;
            *(float2*)&out[(size_t)r1 * CD + col] = o1;
        }
    }
}

// ===========================================================================
extern "C" void kernel_launch(void* const* d_in, const int* in_sizes, int n_in,
                              void* d_out, int out_size) {
    const float* query = (const float*)d_in[0];
    const float* key_  = (const float*)d_in[1];
    const float* value = (const float*)d_in[2];
    const float* Wq = (const float*)d_in[3];
    const float* bq = (const float*)d_in[4];
    const float* Wk = (const float*)d_in[5];
    const float* bk = (const float*)d_in[6];
    const float* Wv = (const float*)d_in[7];
    const float* bv = (const float*)d_in[8];
    const float* Wo = (const float*)d_in[9];
    const float* bo = (const float*)d_in[10];
    const void*  mask = d_in[11];

    float* out = (float*)d_out;
    float *qp, *kp, *vp, *attn;
    cudaGetSymbolAddress((void**)&qp, g_q);
    cudaGetSymbolAddress((void**)&kp, g_k);
    cudaGetSymbolAddress((void**)&vp, g_v);
    if ((size_t)out_size >= (size_t)OUT_ELEMS + ATTN_ELEMS) {
        attn = out + OUT_ELEMS;
    } else {
        cudaGetSymbolAddress((void**)&attn, g_attn_fb);
    }

    detect_mask_kernel<<<1, 1>>>((const uint32_t*)mask);

    dim3 pg(CD/128, CM/128);
    proj_mma<<<pg, 256>>>(query, Wq, bq, qp);
    proj_mma<<<pg, 256>>>(key_,  Wk, bk, kp);
    proj_mma<<<pg, 256>>>(value, Wv, bv, vp);

    qk_mma<<<dim3(CS/128, CS/128, CBH), 256>>>(mask, attn);
    stat_reduce<<<CBH*CS/256, 256>>>();
    pv_mma<<<dim3(CS/256, CBH), 256>>>(attn);
    outproj_mma<<<dim3(CD/128, CM/128), 256>>>(Wo, bo, out);
}

// round 6
// speedup vs baseline: 1.4723x; 1.4723x over previous
#include <cuda_runtime.h>
#include <cstdint>

#define CB 2
#define CS 2048
#define CD 1024
#define CH 16
#define CHD 64
#define CBH (CB*CH)
#define CM (CB*CS)
#define OUT_ELEMS (CB*CS*CD)
#define ATTN_ELEMS ((size_t)CBH*CS*CS)

__device__ float g_q[CBH*CS*CHD];
__device__ float g_k[CBH*CS*CHD];
__device__ float g_v[CBH*CS*CHD];
__device__ float g_ctx[CBH*CS*CHD];
__device__ float g_attn_fb[(size_t)CBH*CS*CS];
__device__ int   g_mask_mode;

#define NEG_INF __int_as_float(0xff800000)

__global__ void detect_mask_kernel(const uint32_t* __restrict__ mask) {
    uint32_t w = mask[0];
    int mode = 0;
    if (w == 0x01010101u)      mode = 0;  // uint8 bool
    else if (w == 1u)          mode = 1;  // int32
    else if (w == 0x3F800000u) mode = 2;  // float32
    g_mask_mode = mode;
}

__device__ __forceinline__ uint32_t f2tf(float f) {
    uint32_t r;
    asm("cvt.rna.tf32.f32 %0, %1;" : "=r"(r) : "f"(f));
    return r;
}

__device__ __forceinline__ void mma8(float* c, const uint32_t* a, const uint32_t* b) {
    asm volatile(
        "mma.sync.aligned.m16n8k8.row.col.f32.tf32.tf32.f32 "
        "{%0,%1,%2,%3}, {%4,%5,%6,%7}, {%8,%9}, {%0,%1,%2,%3};"
        : "+f"(c[0]), "+f"(c[1]), "+f"(c[2]), "+f"(c[3])
        : "r"(a[0]), "r"(a[1]), "r"(a[2]), "r"(a[3]), "r"(b[0]), "r"(b[1]));
}

__device__ __forceinline__ void cpa16(const void* smem, const void* gmem) {
    uint32_t s = (uint32_t)__cvta_generic_to_shared(smem);
    asm volatile("cp.async.cg.shared.global [%0], [%1], 16;" :: "r"(s), "l"(gmem));
}
#define CP_COMMIT() asm volatile("cp.async.commit_group;")
#define CP_WAIT0()  asm volatile("cp.async.wait_group 0;")

// ===========================================================================
// proj: C[4096x1024] = A @ W + bias, scatter to [B,H,S,HD].
// CTA 128x128, BK=16, 256 thr, 8 warps of 64x32. cp.async producers,
// natural-layout smem (A [m][k] pad->20, B [k][n] pad->136), consumer cvt.
// ===========================================================================
__global__ void __launch_bounds__(256,2) proj_mma(
    const float* __restrict__ A, const float* __restrict__ W,
    const float* __restrict__ bias, float* __restrict__ dst)
{
    __shared__ float sA[2][128][20];
    __shared__ float sB[2][16][136];
    const int tid = threadIdx.x, warp = tid >> 5, lane = tid & 31;
    const int g = lane >> 2, tg = lane & 3;
    const int m0 = blockIdx.y * 128, n0 = blockIdx.x * 128;
    const int wm = (warp & 1) * 64, wn = (warp >> 1) * 32;

    const int arow = tid >> 2, aq = (tid & 3) * 4;
    const int brow = tid >> 5, bq = (tid & 31) * 4;

    auto loadAB = [&](int buf, int k0) {
        cpa16(&sA[buf][arow][aq],      A + (size_t)(m0 + arow) * CD + k0 + aq);
        cpa16(&sA[buf][64 + arow][aq], A + (size_t)(m0 + 64 + arow) * CD + k0 + aq);
        cpa16(&sB[buf][brow][bq],      W + (size_t)(k0 + brow) * CD + n0 + bq);
        cpa16(&sB[buf][8 + brow][bq],  W + (size_t)(k0 + 8 + brow) * CD + n0 + bq);
        CP_COMMIT();
    };

    loadAB(0, 0);
    CP_WAIT0();
    __syncthreads();

    float acc[4][4][4] = {};
    int buf = 0;
    for (int c = 1; c <= 64; ++c) {
        const bool more = c < 64;
        if (more) loadAB(buf ^ 1, c * 16);
        #pragma unroll
        for (int ks = 0; ks < 2; ++ks) {
            const int kk = ks*8 + tg;
            uint32_t au[4][4], bu[4][2];
            #pragma unroll
            for (int i = 0; i < 4; ++i) {
                int m = wm + i*16 + g;
                au[i][0] = f2tf(sA[buf][m][kk]);
                au[i][1] = f2tf(sA[buf][m+8][kk]);
                au[i][2] = f2tf(sA[buf][m][kk+4]);
                au[i][3] = f2tf(sA[buf][m+8][kk+4]);
            }
            #pragma unroll
            for (int j = 0; j < 4; ++j) {
                int n = wn + j*8 + g;
                bu[j][0] = f2tf(sB[buf][kk][n]);
                bu[j][1] = f2tf(sB[buf][kk+4][n]);
            }
            #pragma unroll
            for (int i = 0; i < 4; ++i)
                #pragma unroll
                for (int j = 0; j < 4; ++j)
                    mma8(acc[i][j], au[i], bu[j]);
        }
        if (more) {
            CP_WAIT0();
            __syncthreads();
            buf ^= 1;
        }
    }

    #pragma unroll
    for (int i = 0; i < 4; ++i) {
        int r0 = m0 + wm + i*16 + g;
        int r1 = r0 + 8;
        int b0i = r0 >> 11, s0 = r0 & (CS-1);
        int b1i = r1 >> 11, s1 = r1 & (CS-1);
        #pragma unroll
        for (int j = 0; j < 4; ++j) {
            int col = n0 + wn + j*8 + 2*tg;
            int h = col >> 6, hd = col & 63;
            float2 bb = *(const float2*)(bias + col);
            float2 o0 = { acc[i][j][0] + bb.x, acc[i][j][1] + bb.y };
            float2 o1 = { acc[i][j][2] + bb.x, acc[i][j][3] + bb.y };
            *(float2*)&dst[((size_t)(b0i*CH + h)*CS + s0)*CHD + hd] = o0;
            *(float2*)&dst[((size_t)(b1i*CH + h)*CS + s1)*CHD + hd] = o1;
        }
    }
}

// ===========================================================================
// qk: scores = scale * Q @ K^T, masked. CTA 128x128, K=64 in 4 chunks of 16.
// Q smem [m][d] pad20, K smem [n][d] pad20.
// ===========================================================================
__global__ void __launch_bounds__(256,2) qk_mma(
    const void* __restrict__ maskp, float* __restrict__ scores)
{
    __shared__ float sQ[2][128][20];
    __shared__ float sK[2][128][20];
    const int tid = threadIdx.x, warp = tid >> 5, lane = tid & 31;
    const int g = lane >> 2, tg = lane & 3;
    const int bh = blockIdx.z;
    const int q0 = blockIdx.y * 128, k0t = blockIdx.x * 128;
    const int wm = (warp & 1) * 64, wn = (warp >> 1) * 32;
    const float* Qb = g_q + (size_t)bh * CS * CHD;
    const float* Kb = g_k + (size_t)bh * CS * CHD;

    const int arow = tid >> 2, aq = (tid & 3) * 4;

    auto loadQK = [&](int buf, int d0) {
        cpa16(&sQ[buf][arow][aq],      Qb + (size_t)(q0 + arow) * CHD + d0 + aq);
        cpa16(&sQ[buf][64 + arow][aq], Qb + (size_t)(q0 + 64 + arow) * CHD + d0 + aq);
        cpa16(&sK[buf][arow][aq],      Kb + (size_t)(k0t + arow) * CHD + d0 + aq);
        cpa16(&sK[buf][64 + arow][aq], Kb + (size_t)(k0t + 64 + arow) * CHD + d0 + aq);
        CP_COMMIT();
    };

    loadQK(0, 0);
    CP_WAIT0();
    __syncthreads();

    float acc[4][4][4] = {};
    int buf = 0;
    for (int c = 1; c <= 4; ++c) {
        const bool more = c < 4;
        if (more) loadQK(buf ^ 1, c * 16);
        #pragma unroll
        for (int ks = 0; ks < 2; ++ks) {
            const int kk = ks*8 + tg;
            uint32_t au[4][4], bu[4][2];
            #pragma unroll
            for (int i = 0; i < 4; ++i) {
                int m = wm + i*16 + g;
                au[i][0] = f2tf(sQ[buf][m][kk]);
                au[i][1] = f2tf(sQ[buf][m+8][kk]);
                au[i][2] = f2tf(sQ[buf][m][kk+4]);
                au[i][3] = f2tf(sQ[buf][m+8][kk+4]);
            }
            #pragma unroll
            for (int j = 0; j < 4; ++j) {
                int n = wn + j*8 + g;
                bu[j][0] = f2tf(sK[buf][n][kk]);
                bu[j][1] = f2tf(sK[buf][n][kk+4]);
            }
            #pragma unroll
            for (int i = 0; i < 4; ++i)
                #pragma unroll
                for (int j = 0; j < 4; ++j)
                    mma8(acc[i][j], au[i], bu[j]);
        }
        if (more) {
            CP_WAIT0();
            __syncthreads();
            buf ^= 1;
        }
    }

    const int mode = g_mask_mode;
    float* srow = scores + (size_t)bh * CS * CS;
    #pragma unroll
    for (int i = 0; i < 4; ++i) {
        int r0 = q0 + wm + i*16 + g;
        int r1 = r0 + 8;
        #pragma unroll
        for (int j = 0; j < 4; ++j) {
            int col = k0t + wn + j*8 + 2*tg;
            size_t off0 = (size_t)r0 * CS + col;
            size_t off1 = (size_t)r1 * CS + col;
            bool k00, k01, k10, k11;
            if (mode == 0) {
                uchar2 a = *(const uchar2*)((const unsigned char*)maskp + off0);
                uchar2 b = *(const uchar2*)((const unsigned char*)maskp + off1);
                k00 = a.x; k01 = a.y; k10 = b.x; k11 = b.y;
            } else if (mode == 1) {
                int2 a = *(const int2*)((const int*)maskp + off0);
                int2 b = *(const int2*)((const int*)maskp + off1);
                k00 = a.x; k01 = a.y; k10 = b.x; k11 = b.y;
            } else {
                float2 a = *(const float2*)((const float*)maskp + off0);
                float2 b = *(const float2*)((const float*)maskp + off1);
                k00 = a.x != 0.f; k01 = a.y != 0.f; k10 = b.x != 0.f; k11 = b.y != 0.f;
            }
            float2 o0 = { k00 ? acc[i][j][0]*0.125f : NEG_INF,
                          k01 ? acc[i][j][1]*0.125f : NEG_INF };
            float2 o1 = { k10 ? acc[i][j][2]*0.125f : NEG_INF,
                          k11 ? acc[i][j][3]*0.125f : NEG_INF };
            *(float2*)(srow + off0) = o0;
            *(float2*)(srow + off1) = o1;
        }
    }
}

// ===========================================================================
// softmax (R4 version, in place)
// ===========================================================================
__global__ void __launch_bounds__(256) softmax_kernel(float* __restrict__ attn)
{
    float* p = attn + (size_t)blockIdx.x * CS;
    const int tid = threadIdx.x;
    float v[8];
    #pragma unroll
    for (int i = 0; i < 8; ++i) v[i] = p[tid + i*256];
    float m = v[0];
    #pragma unroll
    for (int i = 1; i < 8; ++i) m = fmaxf(m, v[i]);
    __shared__ float redm[8], reds[8];
    #pragma unroll
    for (int o = 16; o > 0; o >>= 1) m = fmaxf(m, __shfl_xor_sync(0xffffffffu, m, o));
    if ((tid & 31) == 0) redm[tid >> 5] = m;
    __syncthreads();
    m = redm[0];
    #pragma unroll
    for (int i = 1; i < 8; ++i) m = fmaxf(m, redm[i]);
    float s = 0.f;
    #pragma unroll
    for (int i = 0; i < 8; ++i) { v[i] = __expf(v[i] - m); s += v[i]; }
    #pragma unroll
    for (int o = 16; o > 0; o >>= 1) s += __shfl_xor_sync(0xffffffffu, s, o);
    if ((tid & 31) == 0) reds[tid >> 5] = s;
    __syncthreads();
    s = 0.f;
    #pragma unroll
    for (int i = 0; i < 8; ++i) s += reds[i];
    float inv = 1.0f / s;
    #pragma unroll
    for (int i = 0; i < 8; ++i) p[tid + i*256] = v[i] * inv;
}

// ===========================================================================
// pv: ctx = attn(2048x2048) @ V(2048x64). CTA 128x64, BK=16, 256 thr,
// 8 warps of 32x32. attn smem [m][k] pad20, V smem [k][n] pad->72.
// ===========================================================================
__global__ void __launch_bounds__(256,2) pv_mma(const float* __restrict__ attn)
{
    __shared__ float sP[2][128][20];
    __shared__ float sV[2][16][72];
    const int tid = threadIdx.x, warp = tid >> 5, lane = tid & 31;
    const int g = lane >> 2, tg = lane & 3;
    const int bh = blockIdx.y, m0 = blockIdx.x * 128;
    const int wm = (warp & 3) * 32, wn = (warp >> 2) * 32;
    const float* Ab = attn + (size_t)bh * CS * CS;
    const float* Vb = g_v + (size_t)bh * CS * CHD;

    const int arow = tid >> 2, aq = (tid & 3) * 4;
    const int vrow = tid >> 4, vq = (tid & 15) * 4;

    auto loadPV = [&](int buf, int k0) {
        cpa16(&sP[buf][arow][aq],      Ab + (size_t)(m0 + arow) * CS + k0 + aq);
        cpa16(&sP[buf][64 + arow][aq], Ab + (size_t)(m0 + 64 + arow) * CS + k0 + aq);
        cpa16(&sV[buf][vrow][vq],      Vb + (size_t)(k0 + vrow) * CHD + vq);
        CP_COMMIT();
    };

    loadPV(0, 0);
    CP_WAIT0();
    __syncthreads();

    float acc[2][4][4] = {};
    int buf = 0;
    for (int c = 1; c <= 128; ++c) {
        const bool more = c < 128;
        if (more) loadPV(buf ^ 1, c * 16);
        #pragma unroll
        for (int ks = 0; ks < 2; ++ks) {
            const int kk = ks*8 + tg;
            uint32_t au[2][4], bu[4][2];
            #pragma unroll
            for (int i = 0; i < 2; ++i) {
                int m = wm + i*16 + g;
                au[i][0] = f2tf(sP[buf][m][kk]);
                au[i][1] = f2tf(sP[buf][m+8][kk]);
                au[i][2] = f2tf(sP[buf][m][kk+4]);
                au[i][3] = f2tf(sP[buf][m+8][kk+4]);
            }
            #pragma unroll
            for (int j = 0; j < 4; ++j) {
                int n = wn + j*8 + g;
                bu[j][0] = f2tf(sV[buf][kk][n]);
                bu[j][1] = f2tf(sV[buf][kk+4][n]);
            }
            #pragma unroll
            for (int i = 0; i < 2; ++i)
                #pragma unroll
                for (int j = 0; j < 4; ++j)
                    mma8(acc[i][j], au[i], bu[j]);
        }
        if (more) {
            CP_WAIT0();
            __syncthreads();
            buf ^= 1;
        }
    }

    float* ctxb = g_ctx + (size_t)bh * CS * CHD;
    #pragma unroll
    for (int i = 0; i < 2; ++i) {
        int r0 = m0 + wm + i*16 + g;
        int r1 = r0 + 8;
        #pragma unroll
        for (int j = 0; j < 4; ++j) {
            int col = wn + j*8 + 2*tg;
            float2 o0 = { acc[i][j][0], acc[i][j][1] };
            float2 o1 = { acc[i][j][2], acc[i][j][3] };
            *(float2*)&ctxb[(size_t)r0 * CHD + col] = o0;
            *(float2*)&ctxb[(size_t)r1 * CHD + col] = o1;
        }
    }
}

// ===========================================================================
// outproj: out = ctx(gather [B,H,S,HD] -> [M,1024]) @ Wo + bo. Like proj.
// ===========================================================================
__global__ void __launch_bounds__(256,2) outproj_mma(
    const float* __restrict__ W, const float* __restrict__ bias, float* __restrict__ out)
{
    __shared__ float sA[2][128][20];
    __shared__ float sB[2][16][136];
    const int tid = threadIdx.x, warp = tid >> 5, lane = tid & 31;
    const int g = lane >> 2, tg = lane & 3;
    const int m0 = blockIdx.y * 128, n0 = blockIdx.x * 128;
    const int wm = (warp & 1) * 64, wn = (warp >> 1) * 32;

    const int arow = tid >> 2, aq = (tid & 3) * 4;
    const int brow = tid >> 5, bq = (tid & 31) * 4;

    const int mA0 = m0 + arow,      bA0 = mA0 >> 11, sA0 = mA0 & (CS-1);
    const int mA1 = m0 + 64 + arow, bA1 = mA1 >> 11, sA1 = mA1 & (CS-1);
    const float* ctx0 = g_ctx + ((size_t)bA0*CH*CS + sA0) * CHD;
    const float* ctx1 = g_ctx + ((size_t)bA1*CH*CS + sA1) * CHD;

    auto loadAB = [&](int buf, int k0) {
        int k = k0 + aq;
        int h = k >> 6, hd = k & 63;
        cpa16(&sA[buf][arow][aq],      ctx0 + (size_t)h * CS * CHD + hd);
        cpa16(&sA[buf][64 + arow][aq], ctx1 + (size_t)h * CS * CHD + hd);
        cpa16(&sB[buf][brow][bq],      W + (size_t)(k0 + brow) * CD + n0 + bq);
        cpa16(&sB[buf][8 + brow][bq],  W + (size_t)(k0 + 8 + brow) * CD + n0 + bq);
        CP_COMMIT();
    };

    loadAB(0, 0);
    CP_WAIT0();
    __syncthreads();

    float acc[4][4][4] = {};
    int buf = 0;
    for (int c = 1; c <= 64; ++c) {
        const bool more = c < 64;
        if (more) loadAB(buf ^ 1, c * 16);
        #pragma unroll
        for (int ks = 0; ks < 2; ++ks) {
            const int kk = ks*8 + tg;
            uint32_t au[4][4], bu[4][2];
            #pragma unroll
            for (int i = 0; i < 4; ++i) {
                int m = wm + i*16 + g;
                au[i][0] = f2tf(sA[buf][m][kk]);
                au[i][1] = f2tf(sA[buf][m+8][kk]);
                au[i][2] = f2tf(sA[buf][m][kk+4]);
                au[i][3] = f2tf(sA[buf][m+8][kk+4]);
            }
            #pragma unroll
            for (int j = 0; j < 4; ++j) {
                int n = wn + j*8 + g;
                bu[j][0] = f2tf(sB[buf][kk][n]);
                bu[j][1] = f2tf(sB[buf][kk+4][n]);
            }
            #pragma unroll
            for (int i = 0; i < 4; ++i)
                #pragma unroll
                for (int j = 0; j < 4; ++j)
                    mma8(acc[i][j], au[i], bu[j]);
        }
        if (more) {
            CP_WAIT0();
            __syncthreads();
            buf ^= 1;
        }
    }

    #pragma unroll
    for (int i = 0; i < 4; ++i) {
        int r0 = m0 + wm + i*16 + g;
        int r1 = r0 + 8;
        #pragma unroll
        for (int j = 0; j < 4; ++j) {
            int col = n0 + wn + j*8 + 2*tg;
            float2 bb = *(const float2*)(bias + col);
            float2 o0 = { acc[i][j][0] + bb.x, acc[i][j][1] + bb.y };
            float2 o1 = { acc[i][j][2] + bb.x, acc[i][j][3] + bb.y };
            *(float2*)&out[(size_t)r0 * CD + col] = o0;
            *(float2*)&out[(size_t)r1 * CD + col] = o1;
        }
    }
}

// ===========================================================================
extern "C" void kernel_launch(void* const* d_in, const int* in_sizes, int n_in,
                              void* d_out, int out_size) {
    const float* query = (const float*)d_in[0];
    const float* key_  = (const float*)d_in[1];
    const float* value = (const float*)d_in[2];
    const float* Wq = (const float*)d_in[3];
    const float* bq = (const float*)d_in[4];
    const float* Wk = (const float*)d_in[5];
    const float* bk = (const float*)d_in[6];
    const float* Wv = (const float*)d_in[7];
    const float* bv = (const float*)d_in[8];
    const float* Wo = (const float*)d_in[9];
    const float* bo = (const float*)d_in[10];
    const void*  mask = d_in[11];

    float* out = (float*)d_out;
    float *qp, *kp, *vp, *attn;
    cudaGetSymbolAddress((void**)&qp, g_q);
    cudaGetSymbolAddress((void**)&kp, g_k);
    cudaGetSymbolAddress((void**)&vp, g_v);
    if ((size_t)out_size >= (size_t)OUT_ELEMS + ATTN_ELEMS) {
        attn = out + OUT_ELEMS;
    } else {
        cudaGetSymbolAddress((void**)&attn, g_attn_fb);
    }

    detect_mask_kernel<<<1, 1>>>((const uint32_t*)mask);

    dim3 pg(CD/128, CM/128);
    proj_mma<<<pg, 256>>>(query, Wq, bq, qp);
    proj_mma<<<pg, 256>>>(key_,  Wk, bk, kp);
    proj_mma<<<pg, 256>>>(value, Wv, bv, vp);

    qk_mma<<<dim3(CS/128, CS/128, CBH), 256>>>(mask, attn);
    softmax_kernel<<<CBH*CS, 256>>>(attn);
    pv_mma<<<dim3(CS/128, CBH), 256>>>(attn);
    outproj_mma<<<dim3(CD/128, CM/128), 256>>>(Wo, bo, out);
}

// round 8
// speedup vs baseline: 1.4896x; 1.0118x over previous
#include <cuda_runtime.h>
#include <cstdint>

#define CB 2
#define CS 2048
#define CD 1024
#define CH 16
#define CHD 64
#define CBH (CB*CH)
#define CM (CB*CS)
#define OUT_ELEMS (CB*CS*CD)
#define ATTN_ELEMS ((size_t)CBH*CS*CS)

__device__ float g_q[CBH*CS*CHD];
__device__ float g_k[CBH*CS*CHD];
__device__ float g_v[CBH*CS*CHD];
__device__ float g_ctx[CBH*CS*CHD];
__device__ float g_attn_fb[(size_t)CBH*CS*CS];
__device__ float g_qc[CM*CD];       // tf32-rounded inputs
__device__ float g_kc[CM*CD];
__device__ float g_vc[CM*CD];
__device__ float g_wq[CD*CD];       // tf32-rounded weights
__device__ float g_wk[CD*CD];
__device__ float g_wv[CD*CD];
__device__ float g_wo[CD*CD];
__device__ int   g_mask_mode;

#define NEG_INF __int_as_float(0xff800000)

__global__ void detect_mask_kernel(const uint32_t* __restrict__ mask) {
    uint32_t w = mask[0];
    int mode = 0;
    if (w == 0x01010101u)      mode = 0;  // uint8 bool
    else if (w == 1u)          mode = 1;  // int32
    else if (w == 0x3F800000u) mode = 2;  // float32
    g_mask_mode = mode;
}

__device__ __forceinline__ uint32_t f2tf(float f) {
    uint32_t r;
    asm("cvt.rna.tf32.f32 %0, %1;" : "=r"(r) : "f"(f));
    return r;
}
__device__ __forceinline__ float f2tff(float f) { return __uint_as_float(f2tf(f)); }

// round a float array to tf32-representable values (float4 grid-stride)
__global__ void __launch_bounds__(256) tf32_round_kernel(
    const float* __restrict__ src, float* __restrict__ dst, int n4)
{
    int i = blockIdx.x * 256 + threadIdx.x;
    if (i < n4) {
        float4 v = ((const float4*)src)[i];
        v.x = f2tff(v.x); v.y = f2tff(v.y); v.z = f2tff(v.z); v.w = f2tff(v.w);
        ((float4*)dst)[i] = v;
    }
}

__device__ __forceinline__ void mma8(float* c, const uint32_t* a, const uint32_t* b) {
    asm volatile(
        "mma.sync.aligned.m16n8k8.row.col.f32.tf32.tf32.f32 "
        "{%0,%1,%2,%3}, {%4,%5,%6,%7}, {%8,%9}, {%0,%1,%2,%3};"
        : "+f"(c[0]), "+f"(c[1]), "+f"(c[2]), "+f"(c[3])
        : "r"(a[0]), "r"(a[1]), "r"(a[2]), "r"(a[3]), "r"(b[0]), "r"(b[1]));
}

__device__ __forceinline__ void cpa16(const void* smem, const void* gmem) {
    uint32_t s = (uint32_t)__cvta_generic_to_shared(smem);
    asm volatile("cp.async.cg.shared.global [%0], [%1], 16;" :: "r"(s), "l"(gmem));
}
#define CP_COMMIT() asm volatile("cp.async.commit_group;")
#define CP_WAIT0()  asm volatile("cp.async.wait_group 0;")

// ===========================================================================
// proj: C = A @ W + bias, scatter to [B,H,S,HD]. A/W pre-rounded tf32.
// Writes pre-rounded outputs. CTA 128x128, BK=16, 256 thr.
// ===========================================================================
__global__ void __launch_bounds__(256,2) proj_mma(
    const float* __restrict__ A, const float* __restrict__ W,
    const float* __restrict__ bias, float* __restrict__ dst)
{
    __shared__ float sA[2][128][20];
    __shared__ float sB[2][16][136];
    const int tid = threadIdx.x, warp = tid >> 5, lane = tid & 31;
    const int g = lane >> 2, tg = lane & 3;
    const int m0 = blockIdx.y * 128, n0 = blockIdx.x * 128;
    const int wm = (warp & 1) * 64, wn = (warp >> 1) * 32;

    const int arow = tid >> 2, aq = (tid & 3) * 4;
    const int brow = tid >> 5, bq = (tid & 31) * 4;

    auto loadAB = [&](int buf, int k0) {
        cpa16(&sA[buf][arow][aq],      A + (size_t)(m0 + arow) * CD + k0 + aq);
        cpa16(&sA[buf][64 + arow][aq], A + (size_t)(m0 + 64 + arow) * CD + k0 + aq);
        cpa16(&sB[buf][brow][bq],      W + (size_t)(k0 + brow) * CD + n0 + bq);
        cpa16(&sB[buf][8 + brow][bq],  W + (size_t)(k0 + 8 + brow) * CD + n0 + bq);
        CP_COMMIT();
    };

    loadAB(0, 0);
    CP_WAIT0();
    __syncthreads();

    float acc[4][4][4] = {};
    int buf = 0;
    for (int c = 1; c <= 64; ++c) {
        const bool more = c < 64;
        if (more) loadAB(buf ^ 1, c * 16);
        #pragma unroll
        for (int ks = 0; ks < 2; ++ks) {
            const int kk = ks*8 + tg;
            uint32_t au[4][4], bu[4][2];
            #pragma unroll
            for (int i = 0; i < 4; ++i) {
                int m = wm + i*16 + g;
                au[i][0] = __float_as_uint(sA[buf][m][kk]);
                au[i][1] = __float_as_uint(sA[buf][m+8][kk]);
                au[i][2] = __float_as_uint(sA[buf][m][kk+4]);
                au[i][3] = __float_as_uint(sA[buf][m+8][kk+4]);
            }
            #pragma unroll
            for (int j = 0; j < 4; ++j) {
                int n = wn + j*8 + g;
                bu[j][0] = __float_as_uint(sB[buf][kk][n]);
                bu[j][1] = __float_as_uint(sB[buf][kk+4][n]);
            }
            #pragma unroll
            for (int i = 0; i < 4; ++i)
                #pragma unroll
                for (int j = 0; j < 4; ++j)
                    mma8(acc[i][j], au[i], bu[j]);
        }
        if (more) {
            CP_WAIT0();
            __syncthreads();
            buf ^= 1;
        }
    }

    #pragma unroll
    for (int i = 0; i < 4; ++i) {
        int r0 = m0 + wm + i*16 + g;
        int r1 = r0 + 8;
        int b0i = r0 >> 11, s0 = r0 & (CS-1);
        int b1i = r1 >> 11, s1 = r1 & (CS-1);
        #pragma unroll
        for (int j = 0; j < 4; ++j) {
            int col = n0 + wn + j*8 + 2*tg;
            int h = col >> 6, hd = col & 63;
            float2 bb = *(const float2*)(bias + col);
            float2 o0 = { f2tff(acc[i][j][0] + bb.x), f2tff(acc[i][j][1] + bb.y) };
            float2 o1 = { f2tff(acc[i][j][2] + bb.x), f2tff(acc[i][j][3] + bb.y) };
            *(float2*)&dst[((size_t)(b0i*CH + h)*CS + s0)*CHD + hd] = o0;
            *(float2*)&dst[((size_t)(b1i*CH + h)*CS + s1)*CHD + hd] = o1;
        }
    }
}

// ===========================================================================
// qk: scores = scale * Q @ K^T, masked. Q/K pre-rounded -> no cvt.
// ===========================================================================
__global__ void __launch_bounds__(256,2) qk_mma(
    const void* __restrict__ maskp, float* __restrict__ scores)
{
    __shared__ float sQ[2][128][20];
    __shared__ float sK[2][128][20];
    const int tid = threadIdx.x, warp = tid >> 5, lane = tid & 31;
    const int g = lane >> 2, tg = lane & 3;
    const int bh = blockIdx.z;
    const int q0 = blockIdx.y * 128, k0t = blockIdx.x * 128;
    const int wm = (warp & 1) * 64, wn = (warp >> 1) * 32;
    const float* Qb = g_q + (size_t)bh * CS * CHD;
    const float* Kb = g_k + (size_t)bh * CS * CHD;

    const int arow = tid >> 2, aq = (tid & 3) * 4;

    auto loadQK = [&](int buf, int d0) {
        cpa16(&sQ[buf][arow][aq],      Qb + (size_t)(q0 + arow) * CHD + d0 + aq);
        cpa16(&sQ[buf][64 + arow][aq], Qb + (size_t)(q0 + 64 + arow) * CHD + d0 + aq);
        cpa16(&sK[buf][arow][aq],      Kb + (size_t)(k0t + arow) * CHD + d0 + aq);
        cpa16(&sK[buf][64 + arow][aq], Kb + (size_t)(k0t + 64 + arow) * CHD + d0 + aq);
        CP_COMMIT();
    };

    loadQK(0, 0);
    CP_WAIT0();
    __syncthreads();

    float acc[4][4][4] = {};
    int buf = 0;
    for (int c = 1; c <= 4; ++c) {
        const bool more = c < 4;
        if (more) loadQK(buf ^ 1, c * 16);
        #pragma unroll
        for (int ks = 0; ks < 2; ++ks) {
            const int kk = ks*8 + tg;
            uint32_t au[4][4], bu[4][2];
            #pragma unroll
            for (int i = 0; i < 4; ++i) {
                int m = wm + i*16 + g;
                au[i][0] = __float_as_uint(sQ[buf][m][kk]);
                au[i][1] = __float_as_uint(sQ[buf][m+8][kk]);
                au[i][2] = __float_as_uint(sQ[buf][m][kk+4]);
                au[i][3] = __float_as_uint(sQ[buf][m+8][kk+4]);
            }
            #pragma unroll
            for (int j = 0; j < 4; ++j) {
                int n = wn + j*8 + g;
                bu[j][0] = __float_as_uint(sK[buf][n][kk]);
                bu[j][1] = __float_as_uint(sK[buf][n][kk+4]);
            }
            #pragma unroll
            for (int i = 0; i < 4; ++i)
                #pragma unroll
                for (int j = 0; j < 4; ++j)
                    mma8(acc[i][j], au[i], bu[j]);
        }
        if (more) {
            CP_WAIT0();
            __syncthreads();
            buf ^= 1;
        }
    }

    const int mode = g_mask_mode;
    float* srow = scores + (size_t)bh * CS * CS;
    #pragma unroll
    for (int i = 0; i < 4; ++i) {
        int r0 = q0 + wm + i*16 + g;
        int r1 = r0 + 8;
        #pragma unroll
        for (int j = 0; j < 4; ++j) {
            int col = k0t + wn + j*8 + 2*tg;
            size_t off0 = (size_t)r0 * CS + col;
            size_t off1 = (size_t)r1 * CS + col;
            bool k00, k01, k10, k11;
            if (mode == 0) {
                uchar2 a = *(const uchar2*)((const unsigned char*)maskp + off0);
                uchar2 b = *(const uchar2*)((const unsigned char*)maskp + off1);
                k00 = a.x; k01 = a.y; k10 = b.x; k11 = b.y;
            } else if (mode == 1) {
                int2 a = *(const int2*)((const int*)maskp + off0);
                int2 b = *(const int2*)((const int*)maskp + off1);
                k00 = a.x; k01 = a.y; k10 = b.x; k11 = b.y;
            } else {
                float2 a = *(const float2*)((const float*)maskp + off0);
                float2 b = *(const float2*)((const float*)maskp + off1);
                k00 = a.x != 0.f; k01 = a.y != 0.f; k10 = b.x != 0.f; k11 = b.y != 0.f;
            }
            float2 o0 = { k00 ? acc[i][j][0]*0.125f : NEG_INF,
                          k01 ? acc[i][j][1]*0.125f : NEG_INF };
            float2 o1 = { k10 ? acc[i][j][2]*0.125f : NEG_INF,
                          k11 ? acc[i][j][3]*0.125f : NEG_INF };
            *(float2*)(srow + off0) = o0;
            *(float2*)(srow + off1) = o1;
        }
    }
}

// ===========================================================================
// softmax (in place, exact f32 — attn is an output)
// ===========================================================================
__global__ void __launch_bounds__(256) softmax_kernel(float* __restrict__ attn)
{
    float* p = attn + (size_t)blockIdx.x * CS;
    const int tid = threadIdx.x;
    float v[8];
    #pragma unroll
    for (int i = 0; i < 8; ++i) v[i] = p[tid + i*256];
    float m = v[0];
    #pragma unroll
    for (int i = 1; i < 8; ++i) m = fmaxf(m, v[i]);
    __shared__ float redm[8], reds[8];
    #pragma unroll
    for (int o = 16; o > 0; o >>= 1) m = fmaxf(m, __shfl_xor_sync(0xffffffffu, m, o));
    if ((tid & 31) == 0) redm[tid >> 5] = m;
    __syncthreads();
    m = redm[0];
    #pragma unroll
    for (int i = 1; i < 8; ++i) m = fmaxf(m, redm[i]);
    float s = 0.f;
    #pragma unroll
    for (int i = 0; i < 8; ++i) { v[i] = __expf(v[i] - m); s += v[i]; }
    #pragma unroll
    for (int o = 16; o > 0; o >>= 1) s += __shfl_xor_sync(0xffffffffu, s, o);
    if ((tid & 31) == 0) reds[tid >> 5] = s;
    __syncthreads();
    s = 0.f;
    #pragma unroll
    for (int i = 0; i < 8; ++i) s += reds[i];
    float inv = 1.0f / s;
    #pragma unroll
    for (int i = 0; i < 8; ++i) p[tid + i*256] = v[i] * inv;
}

// ===========================================================================
// pv: ctx = attn @ V. V pre-rounded (no cvt); attn needs cvt (A operand).
// Writes pre-rounded ctx. CTA 128x64, 8 warps of 32x32.
// ===========================================================================
__global__ void __launch_bounds__(256,2) pv_mma(const float* __restrict__ attn)
{
    __shared__ float sP[2][128][20];
    __shared__ float sV[2][16][72];
    const int tid = threadIdx.x, warp = tid >> 5, lane = tid & 31;
    const int g = lane >> 2, tg = lane & 3;
    const int bh = blockIdx.y, m0 = blockIdx.x * 128;
    const int wm = (warp & 3) * 32, wn = (warp >> 2) * 32;
    const float* Ab = attn + (size_t)bh * CS * CS;
    const float* Vb = g_v + (size_t)bh * CS * CHD;

    const int arow = tid >> 2, aq = (tid & 3) * 4;
    const int vrow = tid >> 4, vq = (tid & 15) * 4;

    auto loadPV = [&](int buf, int k0) {
        cpa16(&sP[buf][arow][aq],      Ab + (size_t)(m0 + arow) * CS + k0 + aq);
        cpa16(&sP[buf][64 + arow][aq], Ab + (size_t)(m0 + 64 + arow) * CS + k0 + aq);
        cpa16(&sV[buf][vrow][vq],      Vb + (size_t)(k0 + vrow) * CHD + vq);
        CP_COMMIT();
    };

    loadPV(0, 0);
    CP_WAIT0();
    __syncthreads();

    float acc[2][4][4] = {};
    int buf = 0;
    for (int c = 1; c <= 128; ++c) {
        const bool more = c < 128;
        if (more) loadPV(buf ^ 1, c * 16);
        #pragma unroll
        for (int ks = 0; ks < 2; ++ks) {
            const int kk = ks*8 + tg;
            uint32_t au[2][4], bu[4][2];
            #pragma unroll
            for (int i = 0; i < 2; ++i) {
                int m = wm + i*16 + g;
                au[i][0] = f2tf(sP[buf][m][kk]);
                au[i][1] = f2tf(sP[buf][m+8][kk]);
                au[i][2] = f2tf(sP[buf][m][kk+4]);
                au[i][3] = f2tf(sP[buf][m+8][kk+4]);
            }
            #pragma unroll
            for (int j = 0; j < 4; ++j) {
                int n = wn + j*8 + g;
                bu[j][0] = __float_as_uint(sV[buf][kk][n]);
                bu[j][1] = __float_as_uint(sV[buf][kk+4][n]);
            }
            #pragma unroll
            for (int i = 0; i < 2; ++i)
                #pragma unroll
                for (int j = 0; j < 4; ++j)
                    mma8(acc[i][j], au[i], bu[j]);
        }
        if (more) {
            CP_WAIT0();
            __syncthreads();
            buf ^= 1;
        }
    }

    float* ctxb = g_ctx + (size_t)bh * CS * CHD;
    #pragma unroll
    for (int i = 0; i < 2; ++i) {
        int r0 = m0 + wm + i*16 + g;
        int r1 = r0 + 8;
        #pragma unroll
        for (int j = 0; j < 4; ++j) {
            int col = wn + j*8 + 2*tg;
            float2 o0 = { f2tff(acc[i][j][0]), f2tff(acc[i][j][1]) };
            float2 o1 = { f2tff(acc[i][j][2]), f2tff(acc[i][j][3]) };
            *(float2*)&ctxb[(size_t)r0 * CHD + col] = o0;
            *(float2*)&ctxb[(size_t)r1 * CHD + col] = o1;
        }
    }
}

// ===========================================================================
// outproj: out = ctx(gather) @ Wo + bo. ctx/Wo pre-rounded -> no cvt.
// ===========================================================================
__global__ void __launch_bounds__(256,2) outproj_mma(
    const float* __restrict__ W, const float* __restrict__ bias, float* __restrict__ out)
{
    __shared__ float sA[2][128][20];
    __shared__ float sB[2][16][136];
    const int tid = threadIdx.x, warp = tid >> 5, lane = tid & 31;
    const int g = lane >> 2, tg = lane & 3;
    const int m0 = blockIdx.y * 128, n0 = blockIdx.x * 128;
    const int wm = (warp & 1) * 64, wn = (warp >> 1) * 32;

    const int arow = tid >> 2, aq = (tid & 3) * 4;
    const int brow = tid >> 5, bq = (tid & 31) * 4;

    const int mA0 = m0 + arow,      bA0 = mA0 >> 11, sA0 = mA0 & (CS-1);
    const int mA1 = m0 + 64 + arow, bA1 = mA1 >> 11, sA1 = mA1 & (CS-1);
    const float* ctx0 = g_ctx + ((size_t)bA0*CH*CS + sA0) * CHD;
    const float* ctx1 = g_ctx + ((size_t)bA1*CH*CS + sA1) * CHD;

    auto loadAB = [&](int buf, int k0) {
        int k = k0 + aq;
        int h = k >> 6, hd = k & 63;
        cpa16(&sA[buf][arow][aq],      ctx0 + (size_t)h * CS * CHD + hd);
        cpa16(&sA[buf][64 + arow][aq], ctx1 + (size_t)h * CS * CHD + hd);
        cpa16(&sB[buf][brow][bq],      W + (size_t)(k0 + brow) * CD + n0 + bq);
        cpa16(&sB[buf][8 + brow][bq],  W + (size_t)(k0 + 8 + brow) * CD + n0 + bq);
        CP_COMMIT();
    };

    loadAB(0, 0);
    CP_WAIT0();
    __syncthreads();

    float acc[4][4][4] = {};
    int buf = 0;
    for (int c = 1; c <= 64; ++c) {
        const bool more = c < 64;
        if (more) loadAB(buf ^ 1, c * 16);
        #pragma unroll
        for (int ks = 0; ks < 2; ++ks) {
            const int kk = ks*8 + tg;
            uint32_t au[4][4], bu[4][2];
            #pragma unroll
            for (int i = 0; i < 4; ++i) {
                int m = wm + i*16 + g;
                au[i][0] = __float_as_uint(sA[buf][m][kk]);
                au[i][1] = __float_as_uint(sA[buf][m+8][kk]);
                au[i][2] = __float_as_uint(sA[buf][m][kk+4]);
                au[i][3] = __float_as_uint(sA[buf][m+8][kk+4]);
            }
            #pragma unroll
            for (int j = 0; j < 4; ++j) {
                int n = wn + j*8 + g;
                bu[j][0] = __float_as_uint(sB[buf][kk][n]);
                bu[j][1] = __float_as_uint(sB[buf][kk+4][n]);
            }
            #pragma unroll
            for (int i = 0; i < 4; ++i)
                #pragma unroll
                for (int j = 0; j < 4; ++j)
                    mma8(acc[i][j], au[i], bu[j]);
        }
        if (more) {
            CP_WAIT0();
            __syncthreads();
            buf ^= 1;
        }
    }

    #pragma unroll
    for (int i = 0; i < 4; ++i) {
        int r0 = m0 + wm + i*16 + g;
        int r1 = r0 + 8;
        #pragma unroll
        for (int j = 0; j < 4; ++j) {
            int col = n0 + wn + j*8 + 2*tg;
            float2 bb = *(const float2*)(bias + col);
            float2 o0 = { acc[i][j][0] + bb.x, acc[i][j][1] + bb.y };
            float2 o1 = { acc[i][j][2] + bb.x, acc[i][j][3] + bb.y };
            *(float2*)&out[(size_t)r0 * CD + col] = o0;
            *(float2*)&out[(size_t)r1 * CD + col] = o1;
        }
    }
}

// ===========================================================================
extern "C" void kernel_launch(void* const* d_in, const int* in_sizes, int n_in,
                              void* d_out, int out_size) {
    const float* query = (const float*)d_in[0];
    const float* key_  = (const float*)d_in[1];
    const float* value = (const float*)d_in[2];
    const float* Wq = (const float*)d_in[3];
    const float* bq = (const float*)d_in[4];
    const float* Wk = (const float*)d_in[5];
    const float* bk = (const float*)d_in[6];
    const float* Wv = (const float*)d_in[7];
    const float* bv = (const float*)d_in[8];
    const float* Wo = (const float*)d_in[9];
    const float* bo = (const float*)d_in[10];
    const void*  mask = d_in[11];

    float* out = (float*)d_out;
    float *qp, *kp, *vp, *attn;
    float *qc, *kc, *vc, *wq, *wk, *wv, *wo;
    cudaGetSymbolAddress((void**)&qp, g_q);
    cudaGetSymbolAddress((void**)&kp, g_k);
    cudaGetSymbolAddress((void**)&vp, g_v);
    cudaGetSymbolAddress((void**)&qc, g_qc);
    cudaGetSymbolAddress((void**)&kc, g_kc);
    cudaGetSymbolAddress((void**)&vc, g_vc);
    cudaGetSymbolAddress((void**)&wq, g_wq);
    cudaGetSymbolAddress((void**)&wk, g_wk);
    cudaGetSymbolAddress((void**)&wv, g_wv);
    cudaGetSymbolAddress((void**)&wo, g_wo);
    if ((size_t)out_size >= (size_t)OUT_ELEMS + ATTN_ELEMS) {
        attn = out + OUT_ELEMS;
    } else {
        cudaGetSymbolAddress((void**)&attn, g_attn_fb);
    }

    detect_mask_kernel<<<1, 1>>>((const uint32_t*)mask);

    const int N4A = CM*CD/4, N4W = CD*CD/4;
    tf32_round_kernel<<<(N4A+255)/256, 256>>>(query, qc, N4A);
    tf32_round_kernel<<<(N4A+255)/256, 256>>>(key_,  kc, N4A);
    tf32_round_kernel<<<(N4A+255)/256, 256>>>(value, vc, N4A);
    tf32_round_kernel<<<(N4W+255)/256, 256>>>(Wq, wq, N4W);
    tf32_round_kernel<<<(N4W+255)/256, 256>>>(Wk, wk, N4W);
    tf32_round_kernel<<<(N4W+255)/256, 256>>>(Wv, wv, N4W);
    tf32_round_kernel<<<(N4W+255)/256, 256>>>(Wo, wo, N4W);

    dim3 pg(CD/128, CM/128);
    proj_mma<<<pg, 256>>>(qc, wq, bq, qp);
    proj_mma<<<pg, 256>>>(kc, wk, bk, kp);
    proj_mma<<<pg, 256>>>(vc, wv, bv, vp);

    qk_mma<<<dim3(CS/128, CS/128, CBH), 256>>>(mask, attn);
    softmax_kernel<<<CBH*CS, 256>>>(attn);
    pv_mma<<<dim3(CS/128, CBH), 256>>>(attn);
    outproj_mma<<<dim3(CD/128, CM/128), 256>>>(wo, bo, out);
}

// round 9
// speedup vs baseline: 1.5442x; 1.0366x over previous
#include <cuda_runtime.h>
#include <cstdint>

#define CB 2
#define CS 2048
#define CD 1024
#define CH 16
#define CHD 64
#define CBH (CB*CH)
#define CM (CB*CS)
#define OUT_ELEMS (CB*CS*CD)
#define ATTN_ELEMS ((size_t)CBH*CS*CS)

__device__ float g_q[CBH*CS*CHD];
__device__ float g_k[CBH*CS*CHD];
__device__ float g_v[CBH*CS*CHD];
__device__ float g_ctx[CBH*CS*CHD];
__device__ float g_attn_fb[(size_t)CBH*CS*CS];
__device__ float g_qc[CM*CD];
__device__ float g_kc[CM*CD];
__device__ float g_vc[CM*CD];
__device__ float g_wq[CD*CD];
__device__ float g_wk[CD*CD];
__device__ float g_wv[CD*CD];
__device__ float g_wo[CD*CD];
__device__ int   g_mask_mode;

#define NEG_INF __int_as_float(0xff800000)

// smem sizes (bytes)
#define PROJ_SMEM (3*(128*20 + 16*132)*4)   // 56064
#define QK_SMEM   (3*2*128*20*4)            // 61440
#define PV_SMEM   (4*(128*20 + 16*72)*4)    // 59392

__global__ void detect_mask_kernel(const uint32_t* __restrict__ mask) {
    uint32_t w = mask[0];
    int mode = 0;
    if (w == 0x01010101u)      mode = 0;
    else if (w == 1u)          mode = 1;
    else if (w == 0x3F800000u) mode = 2;
    g_mask_mode = mode;
}

__device__ __forceinline__ uint32_t f2tf(float f) {
    uint32_t r;
    asm("cvt.rna.tf32.f32 %0, %1;" : "=r"(r) : "f"(f));
    return r;
}
__device__ __forceinline__ float f2tff(float f) { return __uint_as_float(f2tf(f)); }

__global__ void __launch_bounds__(256) tf32_round_kernel(
    const float* __restrict__ src, float* __restrict__ dst, int n4)
{
    int i = blockIdx.x * 256 + threadIdx.x;
    if (i < n4) {
        float4 v = ((const float4*)src)[i];
        v.x = f2tff(v.x); v.y = f2tff(v.y); v.z = f2tff(v.z); v.w = f2tff(v.w);
        ((float4*)dst)[i] = v;
    }
}

__device__ __forceinline__ void mma8(float* c, const uint32_t* a, const uint32_t* b) {
    asm volatile(
        "mma.sync.aligned.m16n8k8.row.col.f32.tf32.tf32.f32 "
        "{%0,%1,%2,%3}, {%4,%5,%6,%7}, {%8,%9}, {%0,%1,%2,%3};"
        : "+f"(c[0]), "+f"(c[1]), "+f"(c[2]), "+f"(c[3])
        : "r"(a[0]), "r"(a[1]), "r"(a[2]), "r"(a[3]), "r"(b[0]), "r"(b[1]));
}

__device__ __forceinline__ void cpa16(const void* smem, const void* gmem) {
    uint32_t s = (uint32_t)__cvta_generic_to_shared(smem);
    asm volatile("cp.async.cg.shared.global [%0], [%1], 16;" :: "r"(s), "l"(gmem));
}
#define CP_COMMIT() asm volatile("cp.async.commit_group;")
#define CP_WAIT(n)  asm volatile("cp.async.wait_group %0;" :: "n"(n))

// ===========================================================================
// proj: C = A @ W + bias, scatter to [B,H,S,HD]. 3-stage pipeline.
// ===========================================================================
__global__ void __launch_bounds__(256,2) proj_mma(
    const float* __restrict__ A, const float* __restrict__ W,
    const float* __restrict__ bias, float* __restrict__ dst)
{
    extern __shared__ float smem[];
    float (*sA)[128][20] = (float(*)[128][20])smem;            // [3][128][20]
    float (*sB)[16][132] = (float(*)[16][132])(smem + 3*128*20);
    const int tid = threadIdx.x, warp = tid >> 5, lane = tid & 31;
    const int g = lane >> 2, tg = lane & 3;
    const int m0 = blockIdx.y * 128, n0 = blockIdx.x * 128;
    const int wm = (warp & 1) * 64, wn = (warp >> 1) * 32;

    const int arow = tid >> 2, aq = (tid & 3) * 4;
    const int brow = tid >> 5, bq = (tid & 31) * 4;

    auto loadAB = [&](int st, int k0) {
        cpa16(&sA[st][arow][aq],      A + (size_t)(m0 + arow) * CD + k0 + aq);
        cpa16(&sA[st][64 + arow][aq], A + (size_t)(m0 + 64 + arow) * CD + k0 + aq);
        cpa16(&sB[st][brow][bq],      W + (size_t)(k0 + brow) * CD + n0 + bq);
        cpa16(&sB[st][8 + brow][bq],  W + (size_t)(k0 + 8 + brow) * CD + n0 + bq);
        CP_COMMIT();
    };

    loadAB(0, 0);
    loadAB(1, 16);

    float acc[4][4][4] = {};
    int stage = 0;
    for (int c = 0; c < 64; ++c) {
        CP_WAIT(1);
        __syncthreads();
        int pf = c + 2;
        if (pf < 64) {
            int st = stage + 2; if (st >= 3) st -= 3;
            loadAB(st, pf * 16);
        } else CP_COMMIT();
        #pragma unroll
        for (int ks = 0; ks < 2; ++ks) {
            const int kk = ks*8 + tg;
            uint32_t au[4][4], bu[4][2];
            #pragma unroll
            for (int i = 0; i < 4; ++i) {
                int m = wm + i*16 + g;
                au[i][0] = __float_as_uint(sA[stage][m][kk]);
                au[i][1] = __float_as_uint(sA[stage][m+8][kk]);
                au[i][2] = __float_as_uint(sA[stage][m][kk+4]);
                au[i][3] = __float_as_uint(sA[stage][m+8][kk+4]);
            }
            #pragma unroll
            for (int j = 0; j < 4; ++j) {
                int n = wn + j*8 + g;
                bu[j][0] = __float_as_uint(sB[stage][kk][n]);
                bu[j][1] = __float_as_uint(sB[stage][kk+4][n]);
            }
            #pragma unroll
            for (int i = 0; i < 4; ++i)
                #pragma unroll
                for (int j = 0; j < 4; ++j)
                    mma8(acc[i][j], au[i], bu[j]);
        }
        if (++stage >= 3) stage = 0;
    }

    #pragma unroll
    for (int i = 0; i < 4; ++i) {
        int r0 = m0 + wm + i*16 + g;
        int r1 = r0 + 8;
        int b0i = r0 >> 11, s0 = r0 & (CS-1);
        int b1i = r1 >> 11, s1 = r1 & (CS-1);
        #pragma unroll
        for (int j = 0; j < 4; ++j) {
            int col = n0 + wn + j*8 + 2*tg;
            int h = col >> 6, hd = col & 63;
            float2 bb = *(const float2*)(bias + col);
            float2 o0 = { f2tff(acc[i][j][0] + bb.x), f2tff(acc[i][j][1] + bb.y) };
            float2 o1 = { f2tff(acc[i][j][2] + bb.x), f2tff(acc[i][j][3] + bb.y) };
            *(float2*)&dst[((size_t)(b0i*CH + h)*CS + s0)*CHD + hd] = o0;
            *(float2*)&dst[((size_t)(b1i*CH + h)*CS + s1)*CHD + hd] = o1;
        }
    }
}

// ===========================================================================
// qk: scores = scale * Q @ K^T, masked. 3-stage (4 chunks of d=16).
// ===========================================================================
__global__ void __launch_bounds__(256,2) qk_mma(
    const void* __restrict__ maskp, float* __restrict__ scores)
{
    extern __shared__ float smem[];
    float (*sQ)[128][20] = (float(*)[128][20])smem;
    float (*sK)[128][20] = (float(*)[128][20])(smem + 3*128*20);
    const int tid = threadIdx.x, warp = tid >> 5, lane = tid & 31;
    const int g = lane >> 2, tg = lane & 3;
    const int bh = blockIdx.z;
    const int q0 = blockIdx.y * 128, k0t = blockIdx.x * 128;
    const int wm = (warp & 1) * 64, wn = (warp >> 1) * 32;
    const float* Qb = g_q + (size_t)bh * CS * CHD;
    const float* Kb = g_k + (size_t)bh * CS * CHD;

    const int arow = tid >> 2, aq = (tid & 3) * 4;

    auto loadQK = [&](int st, int d0) {
        cpa16(&sQ[st][arow][aq],      Qb + (size_t)(q0 + arow) * CHD + d0 + aq);
        cpa16(&sQ[st][64 + arow][aq], Qb + (size_t)(q0 + 64 + arow) * CHD + d0 + aq);
        cpa16(&sK[st][arow][aq],      Kb + (size_t)(k0t + arow) * CHD + d0 + aq);
        cpa16(&sK[st][64 + arow][aq], Kb + (size_t)(k0t + 64 + arow) * CHD + d0 + aq);
        CP_COMMIT();
    };

    loadQK(0, 0);
    loadQK(1, 16);

    float acc[4][4][4] = {};
    int stage = 0;
    for (int c = 0; c < 4; ++c) {
        CP_WAIT(1);
        __syncthreads();
        int pf = c + 2;
        if (pf < 4) {
            int st = stage + 2; if (st >= 3) st -= 3;
            loadQK(st, pf * 16);
        } else CP_COMMIT();
        #pragma unroll
        for (int ks = 0; ks < 2; ++ks) {
            const int kk = ks*8 + tg;
            uint32_t au[4][4], bu[4][2];
            #pragma unroll
            for (int i = 0; i < 4; ++i) {
                int m = wm + i*16 + g;
                au[i][0] = __float_as_uint(sQ[stage][m][kk]);
                au[i][1] = __float_as_uint(sQ[stage][m+8][kk]);
                au[i][2] = __float_as_uint(sQ[stage][m][kk+4]);
                au[i][3] = __float_as_uint(sQ[stage][m+8][kk+4]);
            }
            #pragma unroll
            for (int j = 0; j < 4; ++j) {
                int n = wn + j*8 + g;
                bu[j][0] = __float_as_uint(sK[stage][n][kk]);
                bu[j][1] = __float_as_uint(sK[stage][n][kk+4]);
            }
            #pragma unroll
            for (int i = 0; i < 4; ++i)
                #pragma unroll
                for (int j = 0; j < 4; ++j)
                    mma8(acc[i][j], au[i], bu[j]);
        }
        if (++stage >= 3) stage = 0;
    }

    const int mode = g_mask_mode;
    float* srow = scores + (size_t)bh * CS * CS;
    #pragma unroll
    for (int i = 0; i < 4; ++i) {
        int r0 = q0 + wm + i*16 + g;
        int r1 = r0 + 8;
        #pragma unroll
        for (int j = 0; j < 4; ++j) {
            int col = k0t + wn + j*8 + 2*tg;
            size_t off0 = (size_t)r0 * CS + col;
            size_t off1 = (size_t)r1 * CS + col;
            bool k00, k01, k10, k11;
            if (mode == 0) {
                uchar2 a = *(const uchar2*)((const unsigned char*)maskp + off0);
                uchar2 b = *(const uchar2*)((const unsigned char*)maskp + off1);
                k00 = a.x; k01 = a.y; k10 = b.x; k11 = b.y;
            } else if (mode == 1) {
                int2 a = *(const int2*)((const int*)maskp + off0);
                int2 b = *(const int2*)((const int*)maskp + off1);
                k00 = a.x; k01 = a.y; k10 = b.x; k11 = b.y;
            } else {
                float2 a = *(const float2*)((const float*)maskp + off0);
                float2 b = *(const float2*)((const float*)maskp + off1);
                k00 = a.x != 0.f; k01 = a.y != 0.f; k10 = b.x != 0.f; k11 = b.y != 0.f;
            }
            float2 o0 = { k00 ? acc[i][j][0]*0.125f : NEG_INF,
                          k01 ? acc[i][j][1]*0.125f : NEG_INF };
            float2 o1 = { k10 ? acc[i][j][2]*0.125f : NEG_INF,
                          k11 ? acc[i][j][3]*0.125f : NEG_INF };
            *(float2*)(srow + off0) = o0;
            *(float2*)(srow + off1) = o1;
        }
    }
}

// ===========================================================================
// softmax (in place, exact f32)
// ===========================================================================
__global__ void __launch_bounds__(256) softmax_kernel(float* __restrict__ attn)
{
    float* p = attn + (size_t)blockIdx.x * CS;
    const int tid = threadIdx.x;
    float v[8];
    #pragma unroll
    for (int i = 0; i < 8; ++i) v[i] = p[tid + i*256];
    float m = v[0];
    #pragma unroll
    for (int i = 1; i < 8; ++i) m = fmaxf(m, v[i]);
    __shared__ float redm[8], reds[8];
    #pragma unroll
    for (int o = 16; o > 0; o >>= 1) m = fmaxf(m, __shfl_xor_sync(0xffffffffu, m, o));
    if ((tid & 31) == 0) redm[tid >> 5] = m;
    __syncthreads();
    m = redm[0];
    #pragma unroll
    for (int i = 1; i < 8; ++i) m = fmaxf(m, redm[i]);
    float s = 0.f;
    #pragma unroll
    for (int i = 0; i < 8; ++i) { v[i] = __expf(v[i] - m); s += v[i]; }
    #pragma unroll
    for (int o = 16; o > 0; o >>= 1) s += __shfl_xor_sync(0xffffffffu, s, o);
    if ((tid & 31) == 0) reds[tid >> 5] = s;
    __syncthreads();
    s = 0.f;
    #pragma unroll
    for (int i = 0; i < 8; ++i) s += reds[i];
    float inv = 1.0f / s;
    #pragma unroll
    for (int i = 0; i < 8; ++i) p[tid + i*256] = v[i] * inv;
}

// ===========================================================================
// pv: ctx = attn @ V. 4-stage pipeline, CTA 128x64.
// ===========================================================================
__global__ void __launch_bounds__(256,2) pv_mma(const float* __restrict__ attn)
{
    extern __shared__ float smem[];
    float (*sP)[128][20] = (float(*)[128][20])smem;            // [4][128][20]
    float (*sV)[16][72]  = (float(*)[16][72])(smem + 4*128*20);
    const int tid = threadIdx.x, warp = tid >> 5, lane = tid & 31;
    const int g = lane >> 2, tg = lane & 3;
    const int bh = blockIdx.y, m0 = blockIdx.x * 128;
    const int wm = (warp & 3) * 32, wn = (warp >> 2) * 32;
    const float* Ab = attn + (size_t)bh * CS * CS;
    const float* Vb = g_v + (size_t)bh * CS * CHD;

    const int arow = tid >> 2, aq = (tid & 3) * 4;
    const int vrow = tid >> 4, vq = (tid & 15) * 4;

    auto loadPV = [&](int st, int k0) {
        cpa16(&sP[st][arow][aq],      Ab + (size_t)(m0 + arow) * CS + k0 + aq);
        cpa16(&sP[st][64 + arow][aq], Ab + (size_t)(m0 + 64 + arow) * CS + k0 + aq);
        cpa16(&sV[st][vrow][vq],      Vb + (size_t)(k0 + vrow) * CHD + vq);
        CP_COMMIT();
    };

    loadPV(0, 0);
    loadPV(1, 16);
    loadPV(2, 32);

    float acc[2][4][4] = {};
    int stage = 0;
    for (int c = 0; c < 128; ++c) {
        CP_WAIT(2);
        __syncthreads();
        int pf = c + 3;
        if (pf < 128) {
            int st = stage + 3; if (st >= 4) st -= 4;
            loadPV(st, pf * 16);
        } else CP_COMMIT();
        #pragma unroll
        for (int ks = 0; ks < 2; ++ks) {
            const int kk = ks*8 + tg;
            uint32_t au[2][4], bu[4][2];
            #pragma unroll
            for (int i = 0; i < 2; ++i) {
                int m = wm + i*16 + g;
                au[i][0] = f2tf(sP[stage][m][kk]);
                au[i][1] = f2tf(sP[stage][m+8][kk]);
                au[i][2] = f2tf(sP[stage][m][kk+4]);
                au[i][3] = f2tf(sP[stage][m+8][kk+4]);
            }
            #pragma unroll
            for (int j = 0; j < 4; ++j) {
                int n = wn + j*8 + g;
                bu[j][0] = __float_as_uint(sV[stage][kk][n]);
                bu[j][1] = __float_as_uint(sV[stage][kk+4][n]);
            }
            #pragma unroll
            for (int i = 0; i < 2; ++i)
                #pragma unroll
                for (int j = 0; j < 4; ++j)
                    mma8(acc[i][j], au[i], bu[j]);
        }
        if (++stage >= 4) stage = 0;
    }

    float* ctxb = g_ctx + (size_t)bh * CS * CHD;
    #pragma unroll
    for (int i = 0; i < 2; ++i) {
        int r0 = m0 + wm + i*16 + g;
        int r1 = r0 + 8;
        #pragma unroll
        for (int j = 0; j < 4; ++j) {
            int col = wn + j*8 + 2*tg;
            float2 o0 = { f2tff(acc[i][j][0]), f2tff(acc[i][j][1]) };
            float2 o1 = { f2tff(acc[i][j][2]), f2tff(acc[i][j][3]) };
            *(float2*)&ctxb[(size_t)r0 * CHD + col] = o0;
            *(float2*)&ctxb[(size_t)r1 * CHD + col] = o1;
        }
    }
}

// ===========================================================================
// outproj: out = ctx(gather) @ Wo + bo. 3-stage pipeline.
// ===========================================================================
__global__ void __launch_bounds__(256,2) outproj_mma(
    const float* __restrict__ W, const float* __restrict__ bias, float* __restrict__ out)
{
    extern __shared__ float smem[];
    float (*sA)[128][20] = (float(*)[128][20])smem;
    float (*sB)[16][132] = (float(*)[16][132])(smem + 3*128*20);
    const int tid = threadIdx.x, warp = tid >> 5, lane = tid & 31;
    const int g = lane >> 2, tg = lane & 3;
    const int m0 = blockIdx.y * 128, n0 = blockIdx.x * 128;
    const int wm = (warp & 1) * 64, wn = (warp >> 1) * 32;

    const int arow = tid >> 2, aq = (tid & 3) * 4;
    const int brow = tid >> 5, bq = (tid & 31) * 4;

    const int mA0 = m0 + arow,      bA0 = mA0 >> 11, sA0 = mA0 & (CS-1);
    const int mA1 = m0 + 64 + arow, bA1 = mA1 >> 11, sA1 = mA1 & (CS-1);
    const float* ctx0 = g_ctx + ((size_t)bA0*CH*CS + sA0) * CHD;
    const float* ctx1 = g_ctx + ((size_t)bA1*CH*CS + sA1) * CHD;

    auto loadAB = [&](int st, int k0) {
        int k = k0 + aq;
        int h = k >> 6, hd = k & 63;
        cpa16(&sA[st][arow][aq],      ctx0 + (size_t)h * CS * CHD + hd);
        cpa16(&sA[st][64 + arow][aq], ctx1 + (size_t)h * CS * CHD + hd);
        cpa16(&sB[st][brow][bq],      W + (size_t)(k0 + brow) * CD + n0 + bq);
        cpa16(&sB[st][8 + brow][bq],  W + (size_t)(k0 + 8 + brow) * CD + n0 + bq);
        CP_COMMIT();
    };

    loadAB(0, 0);
    loadAB(1, 16);

    float acc[4][4][4] = {};
    int stage = 0;
    for (int c = 0; c < 64; ++c) {
        CP_WAIT(1);
        __syncthreads();
        int pf = c + 2;
        if (pf < 64) {
            int st = stage + 2; if (st >= 3) st -= 3;
            loadAB(st, pf * 16);
        } else CP_COMMIT();
        #pragma unroll
        for (int ks = 0; ks < 2; ++ks) {
            const int kk = ks*8 + tg;
            uint32_t au[4][4], bu[4][2];
            #pragma unroll
            for (int i = 0; i < 4; ++i) {
                int m = wm + i*16 + g;
                au[i][0] = __float_as_uint(sA[stage][m][kk]);
                au[i][1] = __float_as_uint(sA[stage][m+8][kk]);
                au[i][2] = __float_as_uint(sA[stage][m][kk+4]);
                au[i][3] = __float_as_uint(sA[stage][m+8][kk+4]);
            }
            #pragma unroll
            for (int j = 0; j < 4; ++j) {
                int n = wn + j*8 + g;
                bu[j][0] = __float_as_uint(sB[stage][kk][n]);
                bu[j][1] = __float_as_uint(sB[stage][kk+4][n]);
            }
            #pragma unroll
            for (int i = 0; i < 4; ++i)
                #pragma unroll
                for (int j = 0; j < 4; ++j)
                    mma8(acc[i][j], au[i], bu[j]);
        }
        if (++stage >= 3) stage = 0;
    }

    #pragma unroll
    for (int i = 0; i < 4; ++i) {
        int r0 = m0 + wm + i*16 + g;
        int r1 = r0 + 8;
        #pragma unroll
        for (int j = 0; j < 4; ++j) {
            int col = n0 + wn + j*8 + 2*tg;
            float2 bb = *(const float2*)(bias + col);
            float2 o0 = { acc[i][j][0] + bb.x, acc[i][j][1] + bb.y };
            float2 o1 = { acc[i][j][2] + bb.x, acc[i][j][3] + bb.y };
            *(float2*)&out[(size_t)r0 * CD + col] = o0;
            *(float2*)&out[(size_t)r1 * CD + col] = o1;
        }
    }
}

// ===========================================================================
extern "C" void kernel_launch(void* const* d_in, const int* in_sizes, int n_in,
                              void* d_out, int out_size) {
    const float* query = (const float*)d_in[0];
    const float* key_  = (const float*)d_in[1];
    const float* value = (const float*)d_in[2];
    const float* Wq = (const float*)d_in[3];
    const float* bq = (const float*)d_in[4];
    const float* Wk = (const float*)d_in[5];
    const float* bk = (const float*)d_in[6];
    const float* Wv = (const float*)d_in[7];
    const float* bv = (const float*)d_in[8];
    const float* Wo = (const float*)d_in[9];
    const float* bo = (const float*)d_in[10];
    const void*  mask = d_in[11];

    float* out = (float*)d_out;
    float *qp, *kp, *vp, *attn;
    float *qc, *kc, *vc, *wq, *wk, *wv, *wo;
    cudaGetSymbolAddress((void**)&qp, g_q);
    cudaGetSymbolAddress((void**)&kp, g_k);
    cudaGetSymbolAddress((void**)&vp, g_v);
    cudaGetSymbolAddress((void**)&qc, g_qc);
    cudaGetSymbolAddress((void**)&kc, g_kc);
    cudaGetSymbolAddress((void**)&vc, g_vc);
    cudaGetSymbolAddress((void**)&wq, g_wq);
    cudaGetSymbolAddress((void**)&wk, g_wk);
    cudaGetSymbolAddress((void**)&wv, g_wv);
    cudaGetSymbolAddress((void**)&wo, g_wo);
    if ((size_t)out_size >= (size_t)OUT_ELEMS + ATTN_ELEMS) {
        attn = out + OUT_ELEMS;
    } else {
        cudaGetSymbolAddress((void**)&attn, g_attn_fb);
    }

    cudaFuncSetAttribute(proj_mma,    cudaFuncAttributeMaxDynamicSharedMemorySize, PROJ_SMEM);
    cudaFuncSetAttribute(qk_mma,      cudaFuncAttributeMaxDynamicSharedMemorySize, QK_SMEM);
    cudaFuncSetAttribute(pv_mma,      cudaFuncAttributeMaxDynamicSharedMemorySize, PV_SMEM);
    cudaFuncSetAttribute(outproj_mma, cudaFuncAttributeMaxDynamicSharedMemorySize, PROJ_SMEM);

    detect_mask_kernel<<<1, 1>>>((const uint32_t*)mask);

    const int N4A = CM*CD/4, N4W = CD*CD/4;
    tf32_round_kernel<<<(N4A+255)/256, 256>>>(query, qc, N4A);
    tf32_round_kernel<<<(N4A+255)/256, 256>>>(key_,  kc, N4A);
    tf32_round_kernel<<<(N4A+255)/256, 256>>>(value, vc, N4A);
    tf32_round_kernel<<<(N4W+255)/256, 256>>>(Wq, wq, N4W);
    tf32_round_kernel<<<(N4W+255)/256, 256>>>(Wk, wk, N4W);
    tf32_round_kernel<<<(N4W+255)/256, 256>>>(Wv, wv, N4W);
    tf32_round_kernel<<<(N4W+255)/256, 256>>>(Wo, wo, N4W);

    dim3 pg(CD/128, CM/128);
    proj_mma<<<pg, 256, PROJ_SMEM>>>(qc, wq, bq, qp);
    proj_mma<<<pg, 256, PROJ_SMEM>>>(kc, wk, bk, kp);
    proj_mma<<<pg, 256, PROJ_SMEM>>>(vc, wv, bv, vp);

    qk_mma<<<dim3(CS/128, CS/128, CBH), 256, QK_SMEM>>>(mask, attn);
    softmax_kernel<<<CBH*CS, 256>>>(attn);
    pv_mma<<<dim3(CS/128, CBH), 256, PV_SMEM>>>(attn);
    outproj_mma<<<dim3(CD/128, CM/128), 256, PROJ_SMEM>>>(wo, bo, out);
}

// round 10
// speedup vs baseline: 1.5648x; 1.0133x over previous
#include <cuda_runtime.h>
#include <cstdint>

#define CB 2
#define CS 2048
#define CD 1024
#define CH 16
#define CHD 64
#define CBH (CB*CH)
#define CM (CB*CS)
#define OUT_ELEMS (CB*CS*CD)
#define ATTN_ELEMS ((size_t)CBH*CS*CS)
#define NKT (CS/128)   // 16 score tiles per row

__device__ float g_q[CBH*CS*CHD];
__device__ float g_k[CBH*CS*CHD];
__device__ float g_v[CBH*CS*CHD];
__device__ float g_ctx[CBH*CS*CHD];
__device__ float g_attn_fb[(size_t)CBH*CS*CS];
__device__ float g_qc[CM*CD];
__device__ float g_kc[CM*CD];
__device__ float g_vc[CM*CD];
__device__ float g_wq[CD*CD];
__device__ float g_wk[CD*CD];
__device__ float g_wv[CD*CD];
__device__ float g_wo[CD*CD];
__device__ float g_stat_max[(size_t)CBH*CS*NKT];
__device__ float g_stat_sum[(size_t)CBH*CS*NKT];
__device__ float g_row_m[CBH*CS];
__device__ float g_row_inv[CBH*CS];
__device__ int   g_mask_mode;

#define NEG_INF __int_as_float(0xff800000)

#define PROJ_SMEM (3*(128*20 + 16*132)*4)
#define QK_SMEM   (3*2*128*20*4)
#define PV_SMEM   (4*(128*20 + 16*72)*4)

__global__ void detect_mask_kernel(const uint32_t* __restrict__ mask) {
    uint32_t w = mask[0];
    int mode = 0;
    if (w == 0x01010101u)      mode = 0;
    else if (w == 1u)          mode = 1;
    else if (w == 0x3F800000u) mode = 2;
    g_mask_mode = mode;
}

__device__ __forceinline__ uint32_t f2tf(float f) {
    uint32_t r;
    asm("cvt.rna.tf32.f32 %0, %1;" : "=r"(r) : "f"(f));
    return r;
}
__device__ __forceinline__ float f2tff(float f) { return __uint_as_float(f2tf(f)); }

__global__ void __launch_bounds__(256) tf32_round_kernel(
    const float* __restrict__ src, float* __restrict__ dst, int n4)
{
    int i = blockIdx.x * 256 + threadIdx.x;
    if (i < n4) {
        float4 v = ((const float4*)src)[i];
        v.x = f2tff(v.x); v.y = f2tff(v.y); v.z = f2tff(v.z); v.w = f2tff(v.w);
        ((float4*)dst)[i] = v;
    }
}

__device__ __forceinline__ void mma8(float* c, const uint32_t* a, const uint32_t* b) {
    asm volatile(
        "mma.sync.aligned.m16n8k8.row.col.f32.tf32.tf32.f32 "
        "{%0,%1,%2,%3}, {%4,%5,%6,%7}, {%8,%9}, {%0,%1,%2,%3};"
        : "+f"(c[0]), "+f"(c[1]), "+f"(c[2]), "+f"(c[3])
        : "r"(a[0]), "r"(a[1]), "r"(a[2]), "r"(a[3]), "r"(b[0]), "r"(b[1]));
}

__device__ __forceinline__ void cpa16(const void* smem, const void* gmem) {
    uint32_t s = (uint32_t)__cvta_generic_to_shared(smem);
    asm volatile("cp.async.cg.shared.global [%0], [%1], 16;" :: "r"(s), "l"(gmem));
}
#define CP_COMMIT() asm volatile("cp.async.commit_group;")
#define CP_WAIT(n)  asm volatile("cp.async.wait_group %0;" :: "n"(n))

// ===========================================================================
// proj (unchanged from R9)
// ===========================================================================
__global__ void __launch_bounds__(256,2) proj_mma(
    const float* __restrict__ A, const float* __restrict__ W,
    const float* __restrict__ bias, float* __restrict__ dst)
{
    extern __shared__ float smem[];
    float (*sA)[128][20] = (float(*)[128][20])smem;
    float (*sB)[16][132] = (float(*)[16][132])(smem + 3*128*20);
    const int tid = threadIdx.x, warp = tid >> 5, lane = tid & 31;
    const int g = lane >> 2, tg = lane & 3;
    const int m0 = blockIdx.y * 128, n0 = blockIdx.x * 128;
    const int wm = (warp & 1) * 64, wn = (warp >> 1) * 32;

    const int arow = tid >> 2, aq = (tid & 3) * 4;
    const int brow = tid >> 5, bq = (tid & 31) * 4;

    auto loadAB = [&](int st, int k0) {
        cpa16(&sA[st][arow][aq],      A + (size_t)(m0 + arow) * CD + k0 + aq);
        cpa16(&sA[st][64 + arow][aq], A + (size_t)(m0 + 64 + arow) * CD + k0 + aq);
        cpa16(&sB[st][brow][bq],      W + (size_t)(k0 + brow) * CD + n0 + bq);
        cpa16(&sB[st][8 + brow][bq],  W + (size_t)(k0 + 8 + brow) * CD + n0 + bq);
        CP_COMMIT();
    };

    loadAB(0, 0);
    loadAB(1, 16);

    float acc[4][4][4] = {};
    int stage = 0;
    for (int c = 0; c < 64; ++c) {
        CP_WAIT(1);
        __syncthreads();
        int pf = c + 2;
        if (pf < 64) {
            int st = stage + 2; if (st >= 3) st -= 3;
            loadAB(st, pf * 16);
        } else CP_COMMIT();
        #pragma unroll
        for (int ks = 0; ks < 2; ++ks) {
            const int kk = ks*8 + tg;
            uint32_t au[4][4], bu[4][2];
            #pragma unroll
            for (int i = 0; i < 4; ++i) {
                int m = wm + i*16 + g;
                au[i][0] = __float_as_uint(sA[stage][m][kk]);
                au[i][1] = __float_as_uint(sA[stage][m+8][kk]);
                au[i][2] = __float_as_uint(sA[stage][m][kk+4]);
                au[i][3] = __float_as_uint(sA[stage][m+8][kk+4]);
            }
            #pragma unroll
            for (int j = 0; j < 4; ++j) {
                int n = wn + j*8 + g;
                bu[j][0] = __float_as_uint(sB[stage][kk][n]);
                bu[j][1] = __float_as_uint(sB[stage][kk+4][n]);
            }
            #pragma unroll
            for (int i = 0; i < 4; ++i)
                #pragma unroll
                for (int j = 0; j < 4; ++j)
                    mma8(acc[i][j], au[i], bu[j]);
        }
        if (++stage >= 3) stage = 0;
    }

    #pragma unroll
    for (int i = 0; i < 4; ++i) {
        int r0 = m0 + wm + i*16 + g;
        int r1 = r0 + 8;
        int b0i = r0 >> 11, s0 = r0 & (CS-1);
        int b1i = r1 >> 11, s1 = r1 & (CS-1);
        #pragma unroll
        for (int j = 0; j < 4; ++j) {
            int col = n0 + wn + j*8 + 2*tg;
            int h = col >> 6, hd = col & 63;
            float2 bb = *(const float2*)(bias + col);
            float2 o0 = { f2tff(acc[i][j][0] + bb.x), f2tff(acc[i][j][1] + bb.y) };
            float2 o1 = { f2tff(acc[i][j][2] + bb.x), f2tff(acc[i][j][3] + bb.y) };
            *(float2*)&dst[((size_t)(b0i*CH + h)*CS + s0)*CHD + hd] = o0;
            *(float2*)&dst[((size_t)(b1i*CH + h)*CS + s1)*CHD + hd] = o1;
        }
    }
}

// ===========================================================================
// qk: raw scores + per-(row, tile) softmax stats.
// ===========================================================================
__global__ void __launch_bounds__(256,2) qk_mma(
    const void* __restrict__ maskp, float* __restrict__ scores)
{
    extern __shared__ float smem[];
    float (*sQ)[128][20] = (float(*)[128][20])smem;
    float (*sK)[128][20] = (float(*)[128][20])(smem + 3*128*20);
    const int tid = threadIdx.x, warp = tid >> 5, lane = tid & 31;
    const int g = lane >> 2, tg = lane & 3;
    const int bh = blockIdx.z;
    const int q0 = blockIdx.y * 128, k0t = blockIdx.x * 128;
    const int wm = (warp & 1) * 64, wn = (warp >> 1) * 32;
    const float* Qb = g_q + (size_t)bh * CS * CHD;
    const float* Kb = g_k + (size_t)bh * CS * CHD;

    const int arow = tid >> 2, aq = (tid & 3) * 4;

    auto loadQK = [&](int st, int d0) {
        cpa16(&sQ[st][arow][aq],      Qb + (size_t)(q0 + arow) * CHD + d0 + aq);
        cpa16(&sQ[st][64 + arow][aq], Qb + (size_t)(q0 + 64 + arow) * CHD + d0 + aq);
        cpa16(&sK[st][arow][aq],      Kb + (size_t)(k0t + arow) * CHD + d0 + aq);
        cpa16(&sK[st][64 + arow][aq], Kb + (size_t)(k0t + 64 + arow) * CHD + d0 + aq);
        CP_COMMIT();
    };

    loadQK(0, 0);
    loadQK(1, 16);

    float acc[4][4][4] = {};
    int stage = 0;
    for (int c = 0; c < 4; ++c) {
        CP_WAIT(1);
        __syncthreads();
        int pf = c + 2;
        if (pf < 4) {
            int st = stage + 2; if (st >= 3) st -= 3;
            loadQK(st, pf * 16);
        } else CP_COMMIT();
        #pragma unroll
        for (int ks = 0; ks < 2; ++ks) {
            const int kk = ks*8 + tg;
            uint32_t au[4][4], bu[4][2];
            #pragma unroll
            for (int i = 0; i < 4; ++i) {
                int m = wm + i*16 + g;
                au[i][0] = __float_as_uint(sQ[stage][m][kk]);
                au[i][1] = __float_as_uint(sQ[stage][m+8][kk]);
                au[i][2] = __float_as_uint(sQ[stage][m][kk+4]);
                au[i][3] = __float_as_uint(sQ[stage][m+8][kk+4]);
            }
            #pragma unroll
            for (int j = 0; j < 4; ++j) {
                int n = wn + j*8 + g;
                bu[j][0] = __float_as_uint(sK[stage][n][kk]);
                bu[j][1] = __float_as_uint(sK[stage][n][kk+4]);
            }
            #pragma unroll
            for (int i = 0; i < 4; ++i)
                #pragma unroll
                for (int j = 0; j < 4; ++j)
                    mma8(acc[i][j], au[i], bu[j]);
        }
        if (++stage >= 3) stage = 0;
    }

    // epilogue: mask+scale into acc, write raw scores
    const int mode = g_mask_mode;
    float* srow = scores + (size_t)bh * CS * CS;
    #pragma unroll
    for (int i = 0; i < 4; ++i) {
        int r0 = q0 + wm + i*16 + g;
        int r1 = r0 + 8;
        #pragma unroll
        for (int j = 0; j < 4; ++j) {
            int col = k0t + wn + j*8 + 2*tg;
            size_t off0 = (size_t)r0 * CS + col;
            size_t off1 = (size_t)r1 * CS + col;
            bool k00, k01, k10, k11;
            if (mode == 0) {
                uchar2 a = *(const uchar2*)((const unsigned char*)maskp + off0);
                uchar2 b = *(const uchar2*)((const unsigned char*)maskp + off1);
                k00 = a.x; k01 = a.y; k10 = b.x; k11 = b.y;
            } else if (mode == 1) {
                int2 a = *(const int2*)((const int*)maskp + off0);
                int2 b = *(const int2*)((const int*)maskp + off1);
                k00 = a.x; k01 = a.y; k10 = b.x; k11 = b.y;
            } else {
                float2 a = *(const float2*)((const float*)maskp + off0);
                float2 b = *(const float2*)((const float*)maskp + off1);
                k00 = a.x != 0.f; k01 = a.y != 0.f; k10 = b.x != 0.f; k11 = b.y != 0.f;
            }
            acc[i][j][0] = k00 ? acc[i][j][0]*0.125f : NEG_INF;
            acc[i][j][1] = k01 ? acc[i][j][1]*0.125f : NEG_INF;
            acc[i][j][2] = k10 ? acc[i][j][2]*0.125f : NEG_INF;
            acc[i][j][3] = k11 ? acc[i][j][3]*0.125f : NEG_INF;
            *(float2*)(srow + off0) = *(float2*)&acc[i][j][0];
            *(float2*)(srow + off1) = *(float2*)&acc[i][j][2];
        }
    }

    // tile stats: per-row max & sumexp over this 128-col tile
    float* sred = smem;          // [4][128]
    float* ssum = smem + 512;    // [4][128]
    const int wnIdx = warp >> 1;
    __syncthreads();

    float rmax[4][2];
    #pragma unroll
    for (int i = 0; i < 4; ++i)
        #pragma unroll
        for (int h = 0; h < 2; ++h) {
            float m = NEG_INF;
            #pragma unroll
            for (int j = 0; j < 4; ++j) {
                m = fmaxf(m, acc[i][j][2*h]);
                m = fmaxf(m, acc[i][j][2*h+1]);
            }
            m = fmaxf(m, __shfl_xor_sync(0xffffffffu, m, 1));
            m = fmaxf(m, __shfl_xor_sync(0xffffffffu, m, 2));
            rmax[i][h] = m;
        }
    if (tg == 0) {
        #pragma unroll
        for (int i = 0; i < 4; ++i)
            #pragma unroll
            for (int h = 0; h < 2; ++h)
                sred[wnIdx*128 + wm + i*16 + h*8 + g] = rmax[i][h];
    }
    __syncthreads();
    #pragma unroll
    for (int i = 0; i < 4; ++i)
        #pragma unroll
        for (int h = 0; h < 2; ++h) {
            int rl = wm + i*16 + h*8 + g;
            rmax[i][h] = fmaxf(fmaxf(sred[rl], sred[128+rl]),
                               fmaxf(sred[256+rl], sred[384+rl]));
        }
    float rsum[4][2];
    #pragma unroll
    for (int i = 0; i < 4; ++i)
        #pragma unroll
        for (int h = 0; h < 2; ++h) {
            float m = rmax[i][h];
            float s = 0.f;
            #pragma unroll
            for (int j = 0; j < 4; ++j) {
                float v0 = acc[i][j][2*h], v1 = acc[i][j][2*h+1];
                s += (v0 == NEG_INF) ? 0.f : __expf(v0 - m);
                s += (v1 == NEG_INF) ? 0.f : __expf(v1 - m);
            }
            s += __shfl_xor_sync(0xffffffffu, s, 1);
            s += __shfl_xor_sync(0xffffffffu, s, 2);
            rsum[i][h] = s;
        }
    if (tg == 0) {
        #pragma unroll
        for (int i = 0; i < 4; ++i)
            #pragma unroll
            for (int h = 0; h < 2; ++h)
                ssum[wnIdx*128 + wm + i*16 + h*8 + g] = rsum[i][h];
    }
    __syncthreads();
    if (wnIdx == 0 && tg == 0) {
        #pragma unroll
        for (int i = 0; i < 4; ++i)
            #pragma unroll
            for (int h = 0; h < 2; ++h) {
                int rl = wm + i*16 + h*8 + g;
                float s = ssum[rl] + ssum[128+rl] + ssum[256+rl] + ssum[384+rl];
                size_t sidx = ((size_t)bh*CS + q0 + rl)*NKT + blockIdx.x;
                g_stat_max[sidx] = rmax[i][h];
                g_stat_sum[sidx] = s;
            }
    }
}

// ===========================================================================
// stat_reduce: merge NKT tile stats per row -> row max M and 1/sum.
// ===========================================================================
__global__ void __launch_bounds__(256) stat_reduce()
{
    int idx = blockIdx.x * 256 + threadIdx.x;
    const float* pm = g_stat_max + (size_t)idx * NKT;
    const float* ps = g_stat_sum + (size_t)idx * NKT;
    float M = NEG_INF;
    #pragma unroll
    for (int t = 0; t < NKT; ++t) M = fmaxf(M, pm[t]);
    float S = 0.f;
    #pragma unroll
    for (int t = 0; t < NKT; ++t) S += ps[t] * __expf(pm[t] - M);
    g_row_m[idx] = M;
    g_row_inv[idx] = 1.0f / S;
}

// ===========================================================================
// pv: reads raw scores, transforms to probs in smem (writes attn output),
// ctx = attn @ V. 4-stage, CTA 128x64.
// ===========================================================================
__global__ void __launch_bounds__(256,2) pv_mma(float* __restrict__ attn)
{
    extern __shared__ float smem[];
    float (*sP)[128][20] = (float(*)[128][20])smem;
    float (*sV)[16][72]  = (float(*)[16][72])(smem + 4*128*20);
    const int tid = threadIdx.x, warp = tid >> 5, lane = tid & 31;
    const int g = lane >> 2, tg = lane & 3;
    const int bh = blockIdx.y, m0 = blockIdx.x * 128;
    const int wm = (warp & 3) * 32, wn = (warp >> 2) * 32;
    float* Ab = attn + (size_t)bh * CS * CS;
    const float* Vb = g_v + (size_t)bh * CS * CHD;

    const int arow = tid >> 2, aq = (tid & 3) * 4;
    const int vrow = tid >> 4, vq = (tid & 15) * 4;

    const float rm0 = g_row_m[bh*CS + m0 + arow];
    const float ri0 = g_row_inv[bh*CS + m0 + arow];
    const float rm1 = g_row_m[bh*CS + m0 + 64 + arow];
    const float ri1 = g_row_inv[bh*CS + m0 + 64 + arow];

    auto loadPV = [&](int st, int k0) {
        cpa16(&sP[st][arow][aq],      Ab + (size_t)(m0 + arow) * CS + k0 + aq);
        cpa16(&sP[st][64 + arow][aq], Ab + (size_t)(m0 + 64 + arow) * CS + k0 + aq);
        cpa16(&sV[st][vrow][vq],      Vb + (size_t)(k0 + vrow) * CHD + vq);
        CP_COMMIT();
    };

    loadPV(0, 0);
    loadPV(1, 16);
    loadPV(2, 32);

    float acc[2][4][4] = {};
    int stage = 0;
    for (int c = 0; c < 128; ++c) {
        CP_WAIT(2);
        __syncthreads();
        // transform phase: raw scores -> probs, store back to smem + attn out
        {
            const int k0 = c * 16;
            float4 v0 = *(float4*)&sP[stage][arow][aq];
            float4 v1 = *(float4*)&sP[stage][64 + arow][aq];
            v0.x = __expf(v0.x - rm0) * ri0;
            v0.y = __expf(v0.y - rm0) * ri0;
            v0.z = __expf(v0.z - rm0) * ri0;
            v0.w = __expf(v0.w - rm0) * ri0;
            v1.x = __expf(v1.x - rm1) * ri1;
            v1.y = __expf(v1.y - rm1) * ri1;
            v1.z = __expf(v1.z - rm1) * ri1;
            v1.w = __expf(v1.w - rm1) * ri1;
            *(float4*)&sP[stage][arow][aq]      = v0;
            *(float4*)&sP[stage][64 + arow][aq] = v1;
            *(float4*)&Ab[(size_t)(m0 + arow) * CS + k0 + aq]      = v0;
            *(float4*)&Ab[(size_t)(m0 + 64 + arow) * CS + k0 + aq] = v1;
        }
        __syncthreads();
        int pf = c + 3;
        if (pf < 128) {
            int st = stage + 3; if (st >= 4) st -= 4;
            loadPV(st, pf * 16);
        } else CP_COMMIT();
        #pragma unroll
        for (int ks = 0; ks < 2; ++ks) {
            const int kk = ks*8 + tg;
            uint32_t au[2][4], bu[4][2];
            #pragma unroll
            for (int i = 0; i < 2; ++i) {
                int m = wm + i*16 + g;
                au[i][0] = f2tf(sP[stage][m][kk]);
                au[i][1] = f2tf(sP[stage][m+8][kk]);
                au[i][2] = f2tf(sP[stage][m][kk+4]);
                au[i][3] = f2tf(sP[stage][m+8][kk+4]);
            }
            #pragma unroll
            for (int j = 0; j < 4; ++j) {
                int n = wn + j*8 + g;
                bu[j][0] = __float_as_uint(sV[stage][kk][n]);
                bu[j][1] = __float_as_uint(sV[stage][kk+4][n]);
            }
            #pragma unroll
            for (int i = 0; i < 2; ++i)
                #pragma unroll
                for (int j = 0; j < 4; ++j)
                    mma8(acc[i][j], au[i], bu[j]);
        }
        if (++stage >= 4) stage = 0;
    }

    float* ctxb = g_ctx + (size_t)bh * CS * CHD;
    #pragma unroll
    for (int i = 0; i < 2; ++i) {
        int r0 = m0 + wm + i*16 + g;
        int r1 = r0 + 8;
        #pragma unroll
        for (int j = 0; j < 4; ++j) {
            int col = wn + j*8 + 2*tg;
            float2 o0 = { f2tff(acc[i][j][0]), f2tff(acc[i][j][1]) };
            float2 o1 = { f2tff(acc[i][j][2]), f2tff(acc[i][j][3]) };
            *(float2*)&ctxb[(size_t)r0 * CHD + col] = o0;
            *(float2*)&ctxb[(size_t)r1 * CHD + col] = o1;
        }
    }
}

// ===========================================================================
// outproj (unchanged from R9)
// ===========================================================================
__global__ void __launch_bounds__(256,2) outproj_mma(
    const float* __restrict__ W, const float* __restrict__ bias, float* __restrict__ out)
{
    extern __shared__ float smem[];
    float (*sA)[128][20] = (float(*)[128][20])smem;
    float (*sB)[16][132] = (float(*)[16][132])(smem + 3*128*20);
    const int tid = threadIdx.x, warp = tid >> 5, lane = tid & 31;
    const int g = lane >> 2, tg = lane & 3;
    const int m0 = blockIdx.y * 128, n0 = blockIdx.x * 128;
    const int wm = (warp & 1) * 64, wn = (warp >> 1) * 32;

    const int arow = tid >> 2, aq = (tid & 3) * 4;
    const int brow = tid >> 5, bq = (tid & 31) * 4;

    const int mA0 = m0 + arow,      bA0 = mA0 >> 11, sA0 = mA0 & (CS-1);
    const int mA1 = m0 + 64 + arow, bA1 = mA1 >> 11, sA1 = mA1 & (CS-1);
    const float* ctx0 = g_ctx + ((size_t)bA0*CH*CS + sA0) * CHD;
    const float* ctx1 = g_ctx + ((size_t)bA1*CH*CS + sA1) * CHD;

    auto loadAB = [&](int st, int k0) {
        int k = k0 + aq;
        int h = k >> 6, hd = k & 63;
        cpa16(&sA[st][arow][aq],      ctx0 + (size_t)h * CS * CHD + hd);
        cpa16(&sA[st][64 + arow][aq], ctx1 + (size_t)h * CS * CHD + hd);
        cpa16(&sB[st][brow][bq],      W + (size_t)(k0 + brow) * CD + n0 + bq);
        cpa16(&sB[st][8 + brow][bq],  W + (size_t)(k0 + 8 + brow) * CD + n0 + bq);
        CP_COMMIT();
    };

    loadAB(0, 0);
    loadAB(1, 16);

    float acc[4][4][4] = {};
    int stage = 0;
    for (int c = 0; c < 64; ++c) {
        CP_WAIT(1);
        __syncthreads();
        int pf = c + 2;
        if (pf < 64) {
            int st = stage + 2; if (st >= 3) st -= 3;
            loadAB(st, pf * 16);
        } else CP_COMMIT();
        #pragma unroll
        for (int ks = 0; ks < 2; ++ks) {
            const int kk = ks*8 + tg;
            uint32_t au[4][4], bu[4][2];
            #pragma unroll
            for (int i = 0; i < 4; ++i) {
                int m = wm + i*16 + g;
                au[i][0] = __float_as_uint(sA[stage][m][kk]);
                au[i][1] = __float_as_uint(sA[stage][m+8][kk]);
                au[i][2] = __float_as_uint(sA[stage][m][kk+4]);
                au[i][3] = __float_as_uint(sA[stage][m+8][kk+4]);
            }
            #pragma unroll
            for (int j = 0; j < 4; ++j) {
                int n = wn + j*8 + g;
                bu[j][0] = __float_as_uint(sB[stage][kk][n]);
                bu[j][1] = __float_as_uint(sB[stage][kk+4][n]);
            }
            #pragma unroll
            for (int i = 0; i < 4; ++i)
                #pragma unroll
                for (int j = 0; j < 4; ++j)
                    mma8(acc[i][j], au[i], bu[j]);
        }
        if (++stage >= 3) stage = 0;
    }

    #pragma unroll
    for (int i = 0; i < 4; ++i) {
        int r0 = m0 + wm + i*16 + g;
        int r1 = r0 + 8;
        #pragma unroll
        for (int j = 0; j < 4; ++j) {
            int col = n0 + wn + j*8 + 2*tg;
            float2 bb = *(const float2*)(bias + col);
            float2 o0 = { acc[i][j][0] + bb.x, acc[i][j][1] + bb.y };
            float2 o1 = { acc[i][j][2] + bb.x, acc[i][j][3] + bb.y };
            *(float2*)&out[(size_t)r0 * CD + col] = o0;
            *(float2*)&out[(size_t)r1 * CD + col] = o1;
        }
    }
}

// ===========================================================================
extern "C" void kernel_launch(void* const* d_in, const int* in_sizes, int n_in,
                              void* d_out, int out_size) {
    const float* query = (const float*)d_in[0];
    const float* key_  = (const float*)d_in[1];
    const float* value = (const float*)d_in[2];
    const float* Wq = (const float*)d_in[3];
    const float* bq = (const float*)d_in[4];
    const float* Wk = (const float*)d_in[5];
    const float* bk = (const float*)d_in[6];
    const float* Wv = (const float*)d_in[7];
    const float* bv = (const float*)d_in[8];
    const float* Wo = (const float*)d_in[9];
    const float* bo = (const float*)d_in[10];
    const void*  mask = d_in[11];

    float* out = (float*)d_out;
    float *qp, *kp, *vp, *attn;
    float *qc, *kc, *vc, *wq, *wk, *wv, *wo;
    cudaGetSymbolAddress((void**)&qp, g_q);
    cudaGetSymbolAddress((void**)&kp, g_k);
    cudaGetSymbolAddress((void**)&vp, g_v);
    cudaGetSymbolAddress((void**)&qc, g_qc);
    cudaGetSymbolAddress((void**)&kc, g_kc);
    cudaGetSymbolAddress((void**)&vc, g_vc);
    cudaGetSymbolAddress((void**)&wq, g_wq);
    cudaGetSymbolAddress((void**)&wk, g_wk);
    cudaGetSymbolAddress((void**)&wv, g_wv);
    cudaGetSymbolAddress((void**)&wo, g_wo);
    if ((size_t)out_size >= (size_t)OUT_ELEMS + ATTN_ELEMS) {
        attn = out + OUT_ELEMS;
    } else {
        cudaGetSymbolAddress((void**)&attn, g_attn_fb);
    }

    cudaFuncSetAttribute(proj_mma,    cudaFuncAttributeMaxDynamicSharedMemorySize, PROJ_SMEM);
    cudaFuncSetAttribute(qk_mma,      cudaFuncAttributeMaxDynamicSharedMemorySize, QK_SMEM);
    cudaFuncSetAttribute(pv_mma,      cudaFuncAttributeMaxDynamicSharedMemorySize, PV_SMEM);
    cudaFuncSetAttribute(outproj_mma, cudaFuncAttributeMaxDynamicSharedMemorySize, PROJ_SMEM);

    detect_mask_kernel<<<1, 1>>>((const uint32_t*)mask);

    const int N4A = CM*CD/4, N4W = CD*CD/4;
    tf32_round_kernel<<<(N4A+255)/256, 256>>>(query, qc, N4A);
    tf32_round_kernel<<<(N4A+255)/256, 256>>>(key_,  kc, N4A);
    tf32_round_kernel<<<(N4A+255)/256, 256>>>(value, vc, N4A);
    tf32_round_kernel<<<(N4W+255)/256, 256>>>(Wq, wq, N4W);
    tf32_round_kernel<<<(N4W+255)/256, 256>>>(Wk, wk, N4W);
    tf32_round_kernel<<<(N4W+255)/256, 256>>>(Wv, wv, N4W);
    tf32_round_kernel<<<(N4W+255)/256, 256>>>(Wo, wo, N4W);

    dim3 pg(CD/128, CM/128);
    proj_mma<<<pg, 256, PROJ_SMEM>>>(qc, wq, bq, qp);
    proj_mma<<<pg, 256, PROJ_SMEM>>>(kc, wk, bk, kp);
    proj_mma<<<pg, 256, PROJ_SMEM>>>(vc, wv, bv, vp);

    qk_mma<<<dim3(CS/128, CS/128, CBH), 256, QK_SMEM>>>(mask, attn);
    stat_reduce<<<CBH*CS/256, 256>>>();
    pv_mma<<<dim3(CS/128, CBH), 256, PV_SMEM>>>(attn);
    outproj_mma<<<dim3(CD/128, CM/128), 256, PROJ_SMEM>>>(wo, bo, out);
}

// round 11
// speedup vs baseline: 1.6002x; 1.0226x over previous
#include <cuda_runtime.h>
#include <cstdint>

#define CB 2
#define CS 2048
#define CD 1024
#define CH 16
#define CHD 64
#define CBH (CB*CH)
#define CM (CB*CS)
#define OUT_ELEMS (CB*CS*CD)
#define ATTN_ELEMS ((size_t)CBH*CS*CS)
#define NKT (CS/128)

__device__ float g_q[CBH*CS*CHD];
__device__ float g_k[CBH*CS*CHD];
__device__ float g_v[CBH*CS*CHD];
__device__ float g_ctx[CBH*CS*CHD];
__device__ float g_attn_fb[(size_t)CBH*CS*CS];
__device__ float g_stat_max[(size_t)CBH*CS*NKT];
__device__ float g_stat_sum[(size_t)CBH*CS*NKT];
__device__ float g_row_m[CBH*CS];
__device__ float g_row_inv[CBH*CS];
__device__ int   g_mask_mode;

#define NEG_INF __int_as_float(0xff800000)

#define PROJ_SMEM (3*(128*20 + 16*132)*4)
#define QK_SMEM   (3*2*128*20*4)
#define PV_SMEM   (4*(128*20 + 16*72)*4)

__global__ void detect_mask_kernel(const uint32_t* __restrict__ mask) {
    uint32_t w = mask[0];
    int mode = 0;
    if (w == 0x01010101u)      mode = 0;
    else if (w == 1u)          mode = 1;
    else if (w == 0x3F800000u) mode = 2;
    g_mask_mode = mode;
}

__device__ __forceinline__ uint32_t f2tf(float f) {
    uint32_t r;
    asm("cvt.rna.tf32.f32 %0, %1;" : "=r"(r) : "f"(f));
    return r;
}
__device__ __forceinline__ float f2tff(float f) { return __uint_as_float(f2tf(f)); }

__device__ __forceinline__ void mma8(float* c, const uint32_t* a, const uint32_t* b) {
    asm volatile(
        "mma.sync.aligned.m16n8k8.row.col.f32.tf32.tf32.f32 "
        "{%0,%1,%2,%3}, {%4,%5,%6,%7}, {%8,%9}, {%0,%1,%2,%3};"
        : "+f"(c[0]), "+f"(c[1]), "+f"(c[2]), "+f"(c[3])
        : "r"(a[0]), "r"(a[1]), "r"(a[2]), "r"(a[3]), "r"(b[0]), "r"(b[1]));
}

__device__ __forceinline__ void cpa16(const void* smem, const void* gmem) {
    uint32_t s = (uint32_t)__cvta_generic_to_shared(smem);
    asm volatile("cp.async.cg.shared.global [%0], [%1], 16;" :: "r"(s), "l"(gmem));
}
#define CP_COMMIT() asm volatile("cp.async.commit_group;")
#define CP_WAIT(n)  asm volatile("cp.async.wait_group %0;" :: "n"(n))

// ===========================================================================
// proj: C = A @ W + bias (A/W unrounded; consumer cvt). Writes rounded dst.
// ===========================================================================
__global__ void __launch_bounds__(256,2) proj_mma(
    const float* __restrict__ A, const float* __restrict__ W,
    const float* __restrict__ bias, float* __restrict__ dst)
{
    extern __shared__ float smem[];
    float (*sA)[128][20] = (float(*)[128][20])smem;
    float (*sB)[16][132] = (float(*)[16][132])(smem + 3*128*20);
    const int tid = threadIdx.x, warp = tid >> 5, lane = tid & 31;
    const int g = lane >> 2, tg = lane & 3;
    const int m0 = blockIdx.y * 128, n0 = blockIdx.x * 128;
    const int wm = (warp & 1) * 64, wn = (warp >> 1) * 32;

    const int arow = tid >> 2, aq = (tid & 3) * 4;
    const int brow = tid >> 5, bq = (tid & 31) * 4;

    auto loadAB = [&](int st, int k0) {
        cpa16(&sA[st][arow][aq],      A + (size_t)(m0 + arow) * CD + k0 + aq);
        cpa16(&sA[st][64 + arow][aq], A + (size_t)(m0 + 64 + arow) * CD + k0 + aq);
        cpa16(&sB[st][brow][bq],      W + (size_t)(k0 + brow) * CD + n0 + bq);
        cpa16(&sB[st][8 + brow][bq],  W + (size_t)(k0 + 8 + brow) * CD + n0 + bq);
        CP_COMMIT();
    };

    loadAB(0, 0);
    loadAB(1, 16);

    float acc[4][4][4] = {};
    int stage = 0;
    for (int c = 0; c < 64; ++c) {
        CP_WAIT(1);
        __syncthreads();
        int pf = c + 2;
        if (pf < 64) {
            int st = stage + 2; if (st >= 3) st -= 3;
            loadAB(st, pf * 16);
        } else CP_COMMIT();
        #pragma unroll
        for (int ks = 0; ks < 2; ++ks) {
            const int kk = ks*8 + tg;
            uint32_t au[4][4], bu[4][2];
            #pragma unroll
            for (int i = 0; i < 4; ++i) {
                int m = wm + i*16 + g;
                au[i][0] = f2tf(sA[stage][m][kk]);
                au[i][1] = f2tf(sA[stage][m+8][kk]);
                au[i][2] = f2tf(sA[stage][m][kk+4]);
                au[i][3] = f2tf(sA[stage][m+8][kk+4]);
            }
            #pragma unroll
            for (int j = 0; j < 4; ++j) {
                int n = wn + j*8 + g;
                bu[j][0] = f2tf(sB[stage][kk][n]);
                bu[j][1] = f2tf(sB[stage][kk+4][n]);
            }
            #pragma unroll
            for (int i = 0; i < 4; ++i)
                #pragma unroll
                for (int j = 0; j < 4; ++j)
                    mma8(acc[i][j], au[i], bu[j]);
        }
        if (++stage >= 3) stage = 0;
    }

    #pragma unroll
    for (int i = 0; i < 4; ++i) {
        int r0 = m0 + wm + i*16 + g;
        int r1 = r0 + 8;
        int b0i = r0 >> 11, s0 = r0 & (CS-1);
        int b1i = r1 >> 11, s1 = r1 & (CS-1);
        #pragma unroll
        for (int j = 0; j < 4; ++j) {
            int col = n0 + wn + j*8 + 2*tg;
            int h = col >> 6, hd = col & 63;
            float2 bb = *(const float2*)(bias + col);
            float2 o0 = { f2tff(acc[i][j][0] + bb.x), f2tff(acc[i][j][1] + bb.y) };
            float2 o1 = { f2tff(acc[i][j][2] + bb.x), f2tff(acc[i][j][3] + bb.y) };
            *(float2*)&dst[((size_t)(b0i*CH + h)*CS + s0)*CHD + hd] = o0;
            *(float2*)&dst[((size_t)(b1i*CH + h)*CS + s1)*CHD + hd] = o1;
        }
    }
}

// ===========================================================================
// qk: raw scores + per-(row, tile) softmax stats. Q/K pre-rounded.
// ===========================================================================
__global__ void __launch_bounds__(256,2) qk_mma(
    const void* __restrict__ maskp, float* __restrict__ scores)
{
    extern __shared__ float smem[];
    float (*sQ)[128][20] = (float(*)[128][20])smem;
    float (*sK)[128][20] = (float(*)[128][20])(smem + 3*128*20);
    const int tid = threadIdx.x, warp = tid >> 5, lane = tid & 31;
    const int g = lane >> 2, tg = lane & 3;
    const int bh = blockIdx.z;
    const int q0 = blockIdx.y * 128, k0t = blockIdx.x * 128;
    const int wm = (warp & 1) * 64, wn = (warp >> 1) * 32;
    const float* Qb = g_q + (size_t)bh * CS * CHD;
    const float* Kb = g_k + (size_t)bh * CS * CHD;

    const int arow = tid >> 2, aq = (tid & 3) * 4;

    auto loadQK = [&](int st, int d0) {
        cpa16(&sQ[st][arow][aq],      Qb + (size_t)(q0 + arow) * CHD + d0 + aq);
        cpa16(&sQ[st][64 + arow][aq], Qb + (size_t)(q0 + 64 + arow) * CHD + d0 + aq);
        cpa16(&sK[st][arow][aq],      Kb + (size_t)(k0t + arow) * CHD + d0 + aq);
        cpa16(&sK[st][64 + arow][aq], Kb + (size_t)(k0t + 64 + arow) * CHD + d0 + aq);
        CP_COMMIT();
    };

    loadQK(0, 0);
    loadQK(1, 16);

    float acc[4][4][4] = {};
    int stage = 0;
    for (int c = 0; c < 4; ++c) {
        CP_WAIT(1);
        __syncthreads();
        int pf = c + 2;
        if (pf < 4) {
            int st = stage + 2; if (st >= 3) st -= 3;
            loadQK(st, pf * 16);
        } else CP_COMMIT();
        #pragma unroll
        for (int ks = 0; ks < 2; ++ks) {
            const int kk = ks*8 + tg;
            uint32_t au[4][4], bu[4][2];
            #pragma unroll
            for (int i = 0; i < 4; ++i) {
                int m = wm + i*16 + g;
                au[i][0] = __float_as_uint(sQ[stage][m][kk]);
                au[i][1] = __float_as_uint(sQ[stage][m+8][kk]);
                au[i][2] = __float_as_uint(sQ[stage][m][kk+4]);
                au[i][3] = __float_as_uint(sQ[stage][m+8][kk+4]);
            }
            #pragma unroll
            for (int j = 0; j < 4; ++j) {
                int n = wn + j*8 + g;
                bu[j][0] = __float_as_uint(sK[stage][n][kk]);
                bu[j][1] = __float_as_uint(sK[stage][n][kk+4]);
            }
            #pragma unroll
            for (int i = 0; i < 4; ++i)
                #pragma unroll
                for (int j = 0; j < 4; ++j)
                    mma8(acc[i][j], au[i], bu[j]);
        }
        if (++stage >= 3) stage = 0;
    }

    const int mode = g_mask_mode;
    float* srow = scores + (size_t)bh * CS * CS;
    #pragma unroll
    for (int i = 0; i < 4; ++i) {
        int r0 = q0 + wm + i*16 + g;
        int r1 = r0 + 8;
        #pragma unroll
        for (int j = 0; j < 4; ++j) {
            int col = k0t + wn + j*8 + 2*tg;
            size_t off0 = (size_t)r0 * CS + col;
            size_t off1 = (size_t)r1 * CS + col;
            bool k00, k01, k10, k11;
            if (mode == 0) {
                uchar2 a = *(const uchar2*)((const unsigned char*)maskp + off0);
                uchar2 b = *(const uchar2*)((const unsigned char*)maskp + off1);
                k00 = a.x; k01 = a.y; k10 = b.x; k11 = b.y;
            } else if (mode == 1) {
                int2 a = *(const int2*)((const int*)maskp + off0);
                int2 b = *(const int2*)((const int*)maskp + off1);
                k00 = a.x; k01 = a.y; k10 = b.x; k11 = b.y;
            } else {
                float2 a = *(const float2*)((const float*)maskp + off0);
                float2 b = *(const float2*)((const float*)maskp + off1);
                k00 = a.x != 0.f; k01 = a.y != 0.f; k10 = b.x != 0.f; k11 = b.y != 0.f;
            }
            acc[i][j][0] = k00 ? acc[i][j][0]*0.125f : NEG_INF;
            acc[i][j][1] = k01 ? acc[i][j][1]*0.125f : NEG_INF;
            acc[i][j][2] = k10 ? acc[i][j][2]*0.125f : NEG_INF;
            acc[i][j][3] = k11 ? acc[i][j][3]*0.125f : NEG_INF;
            *(float2*)(srow + off0) = *(float2*)&acc[i][j][0];
            *(float2*)(srow + off1) = *(float2*)&acc[i][j][2];
        }
    }

    float* sred = smem;
    float* ssum = smem + 512;
    const int wnIdx = warp >> 1;
    __syncthreads();

    float rmax[4][2];
    #pragma unroll
    for (int i = 0; i < 4; ++i)
        #pragma unroll
        for (int h = 0; h < 2; ++h) {
            float m = NEG_INF;
            #pragma unroll
            for (int j = 0; j < 4; ++j) {
                m = fmaxf(m, acc[i][j][2*h]);
                m = fmaxf(m, acc[i][j][2*h+1]);
            }
            m = fmaxf(m, __shfl_xor_sync(0xffffffffu, m, 1));
            m = fmaxf(m, __shfl_xor_sync(0xffffffffu, m, 2));
            rmax[i][h] = m;
        }
    if (tg == 0) {
        #pragma unroll
        for (int i = 0; i < 4; ++i)
            #pragma unroll
            for (int h = 0; h < 2; ++h)
                sred[wnIdx*128 + wm + i*16 + h*8 + g] = rmax[i][h];
    }
    __syncthreads();
    #pragma unroll
    for (int i = 0; i < 4; ++i)
        #pragma unroll
        for (int h = 0; h < 2; ++h) {
            int rl = wm + i*16 + h*8 + g;
            rmax[i][h] = fmaxf(fmaxf(sred[rl], sred[128+rl]),
                               fmaxf(sred[256+rl], sred[384+rl]));
        }
    float rsum[4][2];
    #pragma unroll
    for (int i = 0; i < 4; ++i)
        #pragma unroll
        for (int h = 0; h < 2; ++h) {
            float m = rmax[i][h];
            float s = 0.f;
            #pragma unroll
            for (int j = 0; j < 4; ++j) {
                float v0 = acc[i][j][2*h], v1 = acc[i][j][2*h+1];
                s += (v0 == NEG_INF) ? 0.f : __expf(v0 - m);
                s += (v1 == NEG_INF) ? 0.f : __expf(v1 - m);
            }
            s += __shfl_xor_sync(0xffffffffu, s, 1);
            s += __shfl_xor_sync(0xffffffffu, s, 2);
            rsum[i][h] = s;
        }
    if (tg == 0) {
        #pragma unroll
        for (int i = 0; i < 4; ++i)
            #pragma unroll
            for (int h = 0; h < 2; ++h)
                ssum[wnIdx*128 + wm + i*16 + h*8 + g] = rsum[i][h];
    }
    __syncthreads();
    if (wnIdx == 0 && tg == 0) {
        #pragma unroll
        for (int i = 0; i < 4; ++i)
            #pragma unroll
            for (int h = 0; h < 2; ++h) {
                int rl = wm + i*16 + h*8 + g;
                float s = ssum[rl] + ssum[128+rl] + ssum[256+rl] + ssum[384+rl];
                size_t sidx = ((size_t)bh*CS + q0 + rl)*NKT + blockIdx.x;
                g_stat_max[sidx] = rmax[i][h];
                g_stat_sum[sidx] = s;
            }
    }
}

// ===========================================================================
// stat_reduce
// ===========================================================================
__global__ void __launch_bounds__(256) stat_reduce()
{
    int idx = blockIdx.x * 256 + threadIdx.x;
    const float* pm = g_stat_max + (size_t)idx * NKT;
    const float* ps = g_stat_sum + (size_t)idx * NKT;
    float M = NEG_INF;
    #pragma unroll
    for (int t = 0; t < NKT; ++t) M = fmaxf(M, pm[t]);
    float S = 0.f;
    #pragma unroll
    for (int t = 0; t < NKT; ++t) S += ps[t] * __expf(pm[t] - M);
    g_row_m[idx] = M;
    g_row_inv[idx] = 1.0f / S;
}

// ===========================================================================
// pv: raw scores staged in smem; probs written coalesced to attn (read-only
// phase, no second sync); consumers exp+cvt inline. ctx = attn @ V.
// ===========================================================================
__global__ void __launch_bounds__(256,2) pv_mma(float* __restrict__ attn)
{
    extern __shared__ float smem[];
    float (*sP)[128][20] = (float(*)[128][20])smem;
    float (*sV)[16][72]  = (float(*)[16][72])(smem + 4*128*20);
    const int tid = threadIdx.x, warp = tid >> 5, lane = tid & 31;
    const int g = lane >> 2, tg = lane & 3;
    const int bh = blockIdx.y, m0 = blockIdx.x * 128;
    const int wm = (warp & 3) * 32, wn = (warp >> 2) * 32;
    float* Ab = attn + (size_t)bh * CS * CS;
    const float* Vb = g_v + (size_t)bh * CS * CHD;

    const int arow = tid >> 2, aq = (tid & 3) * 4;
    const int vrow = tid >> 4, vq = (tid & 15) * 4;

    // per-thread row stats: writer rows (arow, 64+arow) and consumer fragment rows
    const float rm0 = g_row_m[bh*CS + m0 + arow];
    const float ri0 = g_row_inv[bh*CS + m0 + arow];
    const float rm1 = g_row_m[bh*CS + m0 + 64 + arow];
    const float ri1 = g_row_inv[bh*CS + m0 + 64 + arow];
    float rmf[2][2], rif[2][2];
    #pragma unroll
    for (int i = 0; i < 2; ++i)
        #pragma unroll
        for (int h = 0; h < 2; ++h) {
            int r = m0 + wm + i*16 + g + h*8;
            rmf[i][h] = g_row_m[bh*CS + r];
            rif[i][h] = g_row_inv[bh*CS + r];
        }

    auto loadPV = [&](int st, int k0) {
        cpa16(&sP[st][arow][aq],      Ab + (size_t)(m0 + arow) * CS + k0 + aq);
        cpa16(&sP[st][64 + arow][aq], Ab + (size_t)(m0 + 64 + arow) * CS + k0 + aq);
        cpa16(&sV[st][vrow][vq],      Vb + (size_t)(k0 + vrow) * CHD + vq);
        CP_COMMIT();
    };

    loadPV(0, 0);
    loadPV(1, 16);
    loadPV(2, 32);

    float acc[2][4][4] = {};
    int stage = 0;
    for (int c = 0; c < 128; ++c) {
        CP_WAIT(2);
        __syncthreads();
        int pf = c + 3;
        if (pf < 128) {
            int st = stage + 3; if (st >= 4) st -= 4;
            loadPV(st, pf * 16);
        } else CP_COMMIT();

        // probs write phase: read raw from smem, exp, coalesced STG to attn
        {
            const int k0 = c * 16;
            float4 v0 = *(float4*)&sP[stage][arow][aq];
            float4 v1 = *(float4*)&sP[stage][64 + arow][aq];
            v0.x = __expf(v0.x - rm0) * ri0;
            v0.y = __expf(v0.y - rm0) * ri0;
            v0.z = __expf(v0.z - rm0) * ri0;
            v0.w = __expf(v0.w - rm0) * ri0;
            v1.x = __expf(v1.x - rm1) * ri1;
            v1.y = __expf(v1.y - rm1) * ri1;
            v1.z = __expf(v1.z - rm1) * ri1;
            v1.w = __expf(v1.w - rm1) * ri1;
            *(float4*)&Ab[(size_t)(m0 + arow) * CS + k0 + aq]      = v0;
            *(float4*)&Ab[(size_t)(m0 + 64 + arow) * CS + k0 + aq] = v1;
        }

        #pragma unroll
        for (int ks = 0; ks < 2; ++ks) {
            const int kk = ks*8 + tg;
            uint32_t au[2][4], bu[4][2];
            #pragma unroll
            for (int i = 0; i < 2; ++i) {
                int m = wm + i*16 + g;
                au[i][0] = f2tf(__expf(sP[stage][m][kk]     - rmf[i][0]) * rif[i][0]);
                au[i][1] = f2tf(__expf(sP[stage][m+8][kk]   - rmf[i][1]) * rif[i][1]);
                au[i][2] = f2tf(__expf(sP[stage][m][kk+4]   - rmf[i][0]) * rif[i][0]);
                au[i][3] = f2tf(__expf(sP[stage][m+8][kk+4] - rmf[i][1]) * rif[i][1]);
            }
            #pragma unroll
            for (int j = 0; j < 4; ++j) {
                int n = wn + j*8 + g;
                bu[j][0] = __float_as_uint(sV[stage][kk][n]);
                bu[j][1] = __float_as_uint(sV[stage][kk+4][n]);
            }
            #pragma unroll
            for (int i = 0; i < 2; ++i)
                #pragma unroll
                for (int j = 0; j < 4; ++j)
                    mma8(acc[i][j], au[i], bu[j]);
        }
        if (++stage >= 4) stage = 0;
    }

    float* ctxb = g_ctx + (size_t)bh * CS * CHD;
    #pragma unroll
    for (int i = 0; i < 2; ++i) {
        int r0 = m0 + wm + i*16 + g;
        int r1 = r0 + 8;
        #pragma unroll
        for (int j = 0; j < 4; ++j) {
            int col = wn + j*8 + 2*tg;
            float2 o0 = { f2tff(acc[i][j][0]), f2tff(acc[i][j][1]) };
            float2 o1 = { f2tff(acc[i][j][2]), f2tff(acc[i][j][3]) };
            *(float2*)&ctxb[(size_t)r0 * CHD + col] = o0;
            *(float2*)&ctxb[(size_t)r1 * CHD + col] = o1;
        }
    }
}

// ===========================================================================
// outproj: out = ctx(gather, pre-rounded) @ Wo(consumer cvt) + bo.
// ===========================================================================
__global__ void __launch_bounds__(256,2) outproj_mma(
    const float* __restrict__ W, const float* __restrict__ bias, float* __restrict__ out)
{
    extern __shared__ float smem[];
    float (*sA)[128][20] = (float(*)[128][20])smem;
    float (*sB)[16][132] = (float(*)[16][132])(smem + 3*128*20);
    const int tid = threadIdx.x, warp = tid >> 5, lane = tid & 31;
    const int g = lane >> 2, tg = lane & 3;
    const int m0 = blockIdx.y * 128, n0 = blockIdx.x * 128;
    const int wm = (warp & 1) * 64, wn = (warp >> 1) * 32;

    const int arow = tid >> 2, aq = (tid & 3) * 4;
    const int brow = tid >> 5, bq = (tid & 31) * 4;

    const int mA0 = m0 + arow,      bA0 = mA0 >> 11, sA0 = mA0 & (CS-1);
    const int mA1 = m0 + 64 + arow, bA1 = mA1 >> 11, sA1 = mA1 & (CS-1);
    const float* ctx0 = g_ctx + ((size_t)bA0*CH*CS + sA0) * CHD;
    const float* ctx1 = g_ctx + ((size_t)bA1*CH*CS + sA1) * CHD;

    auto loadAB = [&](int st, int k0) {
        int k = k0 + aq;
        int h = k >> 6, hd = k & 63;
        cpa16(&sA[st][arow][aq],      ctx0 + (size_t)h * CS * CHD + hd);
        cpa16(&sA[st][64 + arow][aq], ctx1 + (size_t)h * CS * CHD + hd);
        cpa16(&sB[st][brow][bq],      W + (size_t)(k0 + brow) * CD + n0 + bq);
        cpa16(&sB[st][8 + brow][bq],  W + (size_t)(k0 + 8 + brow) * CD + n0 + bq);
        CP_COMMIT();
    };

    loadAB(0, 0);
    loadAB(1, 16);

    float acc[4][4][4] = {};
    int stage = 0;
    for (int c = 0; c < 64; ++c) {
        CP_WAIT(1);
        __syncthreads();
        int pf = c + 2;
        if (pf < 64) {
            int st = stage + 2; if (st >= 3) st -= 3;
            loadAB(st, pf * 16);
        } else CP_COMMIT();
        #pragma unroll
        for (int ks = 0; ks < 2; ++ks) {
            const int kk = ks*8 + tg;
            uint32_t au[4][4], bu[4][2];
            #pragma unroll
            for (int i = 0; i < 4; ++i) {
                int m = wm + i*16 + g;
                au[i][0] = __float_as_uint(sA[stage][m][kk]);
                au[i][1] = __float_as_uint(sA[stage][m+8][kk]);
                au[i][2] = __float_as_uint(sA[stage][m][kk+4]);
                au[i][3] = __float_as_uint(sA[stage][m+8][kk+4]);
            }
            #pragma unroll
            for (int j = 0; j < 4; ++j) {
                int n = wn + j*8 + g;
                bu[j][0] = f2tf(sB[stage][kk][n]);
                bu[j][1] = f2tf(sB[stage][kk+4][n]);
            }
            #pragma unroll
            for (int i = 0; i < 4; ++i)
                #pragma unroll
                for (int j = 0; j < 4; ++j)
                    mma8(acc[i][j], au[i], bu[j]);
        }
        if (++stage >= 3) stage = 0;
    }

    #pragma unroll
    for (int i = 0; i < 4; ++i) {
        int r0 = m0 + wm + i*16 + g;
        int r1 = r0 + 8;
        #pragma unroll
        for (int j = 0; j < 4; ++j) {
            int col = n0 + wn + j*8 + 2*tg;
            float2 bb = *(const float2*)(bias + col);
            float2 o0 = { acc[i][j][0] + bb.x, acc[i][j][1] + bb.y };
            float2 o1 = { acc[i][j][2] + bb.x, acc[i][j][3] + bb.y };
            *(float2*)&out[(size_t)r0 * CD + col] = o0;
            *(float2*)&out[(size_t)r1 * CD + col] = o1;
        }
    }
}

// ===========================================================================
extern "C" void kernel_launch(void* const* d_in, const int* in_sizes, int n_in,
                              void* d_out, int out_size) {
    const float* query = (const float*)d_in[0];
    const float* key_  = (const float*)d_in[1];
    const float* value = (const float*)d_in[2];
    const float* Wq = (const float*)d_in[3];
    const float* bq = (const float*)d_in[4];
    const float* Wk = (const float*)d_in[5];
    const float* bk = (const float*)d_in[6];
    const float* Wv = (const float*)d_in[7];
    const float* bv = (const float*)d_in[8];
    const float* Wo = (const float*)d_in[9];
    const float* bo = (const float*)d_in[10];
    const void*  mask = d_in[11];

    float* out = (float*)d_out;
    float *qp, *kp, *vp, *attn;
    cudaGetSymbolAddress((void**)&qp, g_q);
    cudaGetSymbolAddress((void**)&kp, g_k);
    cudaGetSymbolAddress((void**)&vp, g_v);
    if ((size_t)out_size >= (size_t)OUT_ELEMS + ATTN_ELEMS) {
        attn = out + OUT_ELEMS;
    } else {
        cudaGetSymbolAddress((void**)&attn, g_attn_fb);
    }

    cudaFuncSetAttribute(proj_mma,    cudaFuncAttributeMaxDynamicSharedMemorySize, PROJ_SMEM);
    cudaFuncSetAttribute(qk_mma,      cudaFuncAttributeMaxDynamicSharedMemorySize, QK_SMEM);
    cudaFuncSetAttribute(pv_mma,      cudaFuncAttributeMaxDynamicSharedMemorySize, PV_SMEM);
    cudaFuncSetAttribute(outproj_mma, cudaFuncAttributeMaxDynamicSharedMemorySize, PROJ_SMEM);

    detect_mask_kernel<<<1, 1>>>((const uint32_t*)mask);

    dim3 pg(CD/128, CM/128);
    proj_mma<<<pg, 256, PROJ_SMEM>>>(query, Wq, bq, qp);
    proj_mma<<<pg, 256, PROJ_SMEM>>>(key_,  Wk, bk, kp);
    proj_mma<<<pg, 256, PROJ_SMEM>>>(value, Wv, bv, vp);

    qk_mma<<<dim3(CS/128, CS/128, CBH), 256, QK_SMEM>>>(mask, attn);
    stat_reduce<<<CBH*CS/256, 256>>>();
    pv_mma<<<dim3(CS/128, CBH), 256, PV_SMEM>>>(attn);
    outproj_mma<<<dim3(CD/128, CM/128), 256, PROJ_SMEM>>>(Wo, bo, out);
}